// round 9
// baseline (speedup 1.0000x reference)
#include <cuda_runtime.h>
#include <cuda_bf16.h>
#include <stdint.h>
#include <math.h>

#define SCALE_Q 0.17677669529663687f   // 1/sqrt(32)

// Scratch (static __device__; no allocations allowed)
__device__ __nv_bfloat16 g_qhl[1024*256*64];   // [ih][j][qh(32)|ql(32)] (pre-scaled)
__device__ __nv_bfloat16 g_khl[1024*256*64];   // [ih][j][kh|kl]
__device__ __nv_bfloat16 g_vhl[1024*256*64];   // [ih][j][vh|vl]
__device__ float g_gate[1024*256*32];
__device__ float g_o   [1024*256*32];

__device__ __forceinline__ uint32_t pack_bf2(__nv_bfloat16 a, __nv_bfloat16 b) {
    __nv_bfloat162 t; t.x = a; t.y = b;
    return *reinterpret_cast<uint32_t*>(&t);
}

// m16n8k16 row.col bf16 -> f32 accumulate (sm_80+ PTX, valid on compute_103)
__device__ __forceinline__ void mma16816(float* d, const uint32_t* a,
                                         uint32_t b0, uint32_t b1) {
    asm volatile(
        "mma.sync.aligned.m16n8k16.row.col.f32.bf16.bf16.f32 "
        "{%0,%1,%2,%3}, {%4,%5,%6,%7}, {%8,%9}, {%0,%1,%2,%3};"
        : "+f"(d[0]), "+f"(d[1]), "+f"(d[2]), "+f"(d[3])
        : "r"(a[0]), "r"(a[1]), "r"(a[2]), "r"(a[3]), "r"(b0), "r"(b1));
}

// ---------------------------------------------------------------------------
// Kernel 1: LayerNorm + projections. One thread per (row, head):
// head = blockIdx.x >> 8 (whole warp same head -> stores stay coalesced),
// 262144 threads total (4x the old parallelism), 16KB weights per block.
// ---------------------------------------------------------------------------
__global__ __launch_bounds__(256) void proj_kernel(
    const float* __restrict__ z,  const float* __restrict__ ln_g,
    const float* __restrict__ ln_b,
    const float* __restrict__ Wq, const float* __restrict__ Wk,
    const float* __restrict__ Wv, const float* __restrict__ Wg,
    const float* __restrict__ bg)
{
    __shared__ float sWq[1024], sWk[1024], sWv[1024], sWg[1024];
    __shared__ float sbg[32], sg[32], sb[32];

    const int h = blockIdx.x >> 8;          // grid = 1024 blocks
    const int tid = threadIdx.x;
    for (int idx = tid; idx < 1024; idx += 256) {
        sWq[idx] = Wq[h*1024 + idx]; sWk[idx] = Wk[h*1024 + idx];
        sWv[idx] = Wv[h*1024 + idx]; sWg[idx] = Wg[h*1024 + idx];
    }
    if (tid < 32) {
        sbg[tid] = bg[h*32 + tid];
        sg[tid] = ln_g[tid]; sb[tid] = ln_b[tid];
    }
    __syncthreads();

    const int r = ((blockIdx.x & 255) << 8) + tid;   // 0..65535
    const int i = r >> 8, j = r & 255;

    float x[32];
    const float4* zp = (const float4*)(z + (size_t)r * 32);
    #pragma unroll
    for (int c4 = 0; c4 < 8; ++c4) {
        float4 t = zp[c4];
        x[c4*4+0]=t.x; x[c4*4+1]=t.y; x[c4*4+2]=t.z; x[c4*4+3]=t.w;
    }
    float mu = 0.f;
    #pragma unroll
    for (int c = 0; c < 32; ++c) mu += x[c];
    mu *= (1.f/32.f);
    float var = 0.f;
    #pragma unroll
    for (int c = 0; c < 32; ++c) { float d = x[c]-mu; var += d*d; }
    var *= (1.f/32.f);
    const float inv = rsqrtf(var + 1e-5f);
    float zn[32];
    #pragma unroll
    for (int c = 0; c < 32; ++c) zn[c] = (x[c]-mu)*inv*sg[c] + sb[c];

    const int ih = (i<<2) | h;
    __nv_bfloat16* qrow = g_qhl + ((size_t)ih*256 + j)*64;
    __nv_bfloat16* krow = g_khl + ((size_t)ih*256 + j)*64;
    __nv_bfloat16* vrow = g_vhl + ((size_t)ih*256 + j)*64;
    float* grow = g_gate + ((size_t)ih*256 + j)*32;

    #pragma unroll
    for (int co = 0; co < 32; co += 4) {
        float qv[4], kv[4], vv[4], gv[4];
        #pragma unroll
        for (int u = 0; u < 4; ++u) {
            const int row = co + u;
            const float4* wq4 = (const float4*)(sWq + row*32);
            const float4* wk4 = (const float4*)(sWk + row*32);
            const float4* wv4 = (const float4*)(sWv + row*32);
            const float4* wg4 = (const float4*)(sWg + row*32);
            float dq=0.f, dk=0.f, dv=0.f, dg=0.f;
            #pragma unroll
            for (int c4 = 0; c4 < 8; ++c4) {
                float4 a = wq4[c4], b2 = wk4[c4], cv = wv4[c4], dd = wg4[c4];
                float z0=zn[c4*4], z1=zn[c4*4+1], z2=zn[c4*4+2], z3=zn[c4*4+3];
                dq += z0*a.x +z1*a.y +z2*a.z +z3*a.w;
                dk += z0*b2.x+z1*b2.y+z2*b2.z+z3*b2.w;
                dv += z0*cv.x+z1*cv.y+z2*cv.z+z3*cv.w;
                dg += z0*dd.x+z1*dd.y+z2*dd.z+z3*dd.w;
            }
            qv[u] = dq * SCALE_Q; kv[u] = dk; vv[u] = dv;
            gv[u] = 1.f / (1.f + __expf(-(dg + sbg[row])));
        }
        {
            __nv_bfloat16 hh[4], ll[4];
            #pragma unroll
            for (int u = 0; u < 4; ++u) {
                hh[u] = __float2bfloat16(qv[u]);
                ll[u] = __float2bfloat16(qv[u] - __bfloat162float(hh[u]));
            }
            *(uint2*)(qrow + co)      = make_uint2(pack_bf2(hh[0],hh[1]), pack_bf2(hh[2],hh[3]));
            *(uint2*)(qrow + 32 + co) = make_uint2(pack_bf2(ll[0],ll[1]), pack_bf2(ll[2],ll[3]));
        }
        {
            __nv_bfloat16 hh[4], ll[4];
            #pragma unroll
            for (int u = 0; u < 4; ++u) {
                hh[u] = __float2bfloat16(kv[u]);
                ll[u] = __float2bfloat16(kv[u] - __bfloat162float(hh[u]));
            }
            *(uint2*)(krow + co)      = make_uint2(pack_bf2(hh[0],hh[1]), pack_bf2(hh[2],hh[3]));
            *(uint2*)(krow + 32 + co) = make_uint2(pack_bf2(ll[0],ll[1]), pack_bf2(ll[2],ll[3]));
        }
        {
            __nv_bfloat16 hh[4], ll[4];
            #pragma unroll
            for (int u = 0; u < 4; ++u) {
                hh[u] = __float2bfloat16(vv[u]);
                ll[u] = __float2bfloat16(vv[u] - __bfloat162float(hh[u]));
            }
            *(uint2*)(vrow + co)      = make_uint2(pack_bf2(hh[0],hh[1]), pack_bf2(hh[2],hh[3]));
            *(uint2*)(vrow + 32 + co) = make_uint2(pack_bf2(ll[0],ll[1]), pack_bf2(ll[2],ll[3]));
        }
        *(float4*)(grow + co) = make_float4(gv[0],gv[1],gv[2],gv[3]);
    }
}

// ---------------------------------------------------------------------------
// Kernel 2: HMMA attention. One CTA per (i,h); 8 warps x 32 query rows.
// (unchanged from R8 — correct at rel_err 4.2e-6)
// ---------------------------------------------------------------------------
__global__ __launch_bounds__(256) void attn_kernel()
{
    extern __shared__ __align__(16) char smem[];
    uint32_t* sQ = (uint32_t*)smem;            // 256*36 words = 36864 B
    uint32_t* sK = sQ + 256*36;                // 36864 B
    __nv_bfloat16* sVh = (__nv_bfloat16*)(sK + 256*36);  // 32*264*2 = 16896 B
    __nv_bfloat16* sVl = sVh + 32*264;                   // 16896 B

    const int tid = threadIdx.x;
    const int ih = blockIdx.x;

    {
        const uint2* qg = (const uint2*)(g_qhl + (size_t)ih*16384);
        const uint2* kg = (const uint2*)(g_khl + (size_t)ih*16384);
        uint2* sQ2 = (uint2*)sQ;
        uint2* sK2 = (uint2*)sK;
        for (int x = tid; x < 4096; x += 256) {
            int row = x >> 4, w = x & 15;
            sQ2[row*18 + w] = qg[x];
            sK2[row*18 + w] = kg[x];
        }
    }
    {
        const uint4* vg = (const uint4*)(g_vhl + (size_t)ih*16384) + tid*8;
        uint32_t vb[32];
        #pragma unroll
        for (int t = 0; t < 8; ++t) {
            uint4 u = vg[t];
            vb[t*4+0]=u.x; vb[t*4+1]=u.y; vb[t*4+2]=u.z; vb[t*4+3]=u.w;
        }
        const __nv_bfloat16* vbh = (const __nv_bfloat16*)vb;
        #pragma unroll
        for (int c = 0; c < 32; ++c) {
            sVh[c*264 + tid] = vbh[c];
            sVl[c*264 + tid] = vbh[32 + c];
        }
    }
    __syncthreads();

    const int warp = tid >> 5, lane = tid & 31;
    const int l4 = lane & 3, ld4 = lane >> 2;
    const int m0 = warp * 32;

    uint32_t Qh[2][2][4], Ql[2][2][4];
    #pragma unroll
    for (int mt = 0; mt < 2; ++mt)
    #pragma unroll
    for (int kt = 0; kt < 2; ++kt) {
        const int r = m0 + mt*16 + ld4;
        const uint32_t* p0 = sQ + r*36 + kt*8 + l4;
        const uint32_t* p1 = sQ + (r+8)*36 + kt*8 + l4;
        Qh[mt][kt][0] = p0[0];  Qh[mt][kt][1] = p1[0];
        Qh[mt][kt][2] = p0[4];  Qh[mt][kt][3] = p1[4];
        Ql[mt][kt][0] = p0[16]; Ql[mt][kt][1] = p1[16];
        Ql[mt][kt][2] = p0[20]; Ql[mt][kt][3] = p1[20];
    }

    float acc[2][4][4];
    #pragma unroll
    for (int mt = 0; mt < 2; ++mt)
    #pragma unroll
    for (int nt = 0; nt < 4; ++nt)
    #pragma unroll
    for (int u = 0; u < 4; ++u) acc[mt][nt][u] = 0.f;
    float dsum[2][2] = {{0.f,0.f},{0.f,0.f}};

    const uint32_t* sVhw = (const uint32_t*)sVh;
    const uint32_t* sVlw = (const uint32_t*)sVl;

    for (int ch = 0; ch < 8; ++ch) {
        uint32_t Pha[2][2][4], Pla[2][2][4];
        #pragma unroll
        for (int nt = 0; nt < 4; ++nt) {
            const int n = ch*32 + nt*8 + ld4;
            const uint32_t* kp = sK + n*36 + l4;
            uint32_t bh[2][2], bl[2][2];
            bh[0][0]=kp[0];  bh[0][1]=kp[4];  bh[1][0]=kp[8];  bh[1][1]=kp[12];
            bl[0][0]=kp[16]; bl[0][1]=kp[20]; bl[1][0]=kp[24]; bl[1][1]=kp[28];
            #pragma unroll
            for (int mt = 0; mt < 2; ++mt) {
                float s[4] = {0.f,0.f,0.f,0.f};
                mma16816(s, Qh[mt][0], bh[0][0], bh[0][1]);
                mma16816(s, Qh[mt][1], bh[1][0], bh[1][1]);
                mma16816(s, Qh[mt][0], bl[0][0], bl[0][1]);
                mma16816(s, Qh[mt][1], bl[1][0], bl[1][1]);
                mma16816(s, Ql[mt][0], bh[0][0], bh[0][1]);
                mma16816(s, Ql[mt][1], bh[1][0], bh[1][1]);
                const float e0 = __expf(s[0]), e1 = __expf(s[1]);
                const float e2 = __expf(s[2]), e3 = __expf(s[3]);
                dsum[mt][0] += e0 + e1;
                dsum[mt][1] += e2 + e3;
                __nv_bfloat16 h0 = __float2bfloat16(e0), h1 = __float2bfloat16(e1);
                __nv_bfloat16 h2 = __float2bfloat16(e2), h3 = __float2bfloat16(e3);
                const int kt = nt >> 1, half = (nt & 1) * 2;
                Pha[mt][kt][half+0] = pack_bf2(h0, h1);
                Pha[mt][kt][half+1] = pack_bf2(h2, h3);
                Pla[mt][kt][half+0] = pack_bf2(
                    __float2bfloat16(e0 - __bfloat162float(h0)),
                    __float2bfloat16(e1 - __bfloat162float(h1)));
                Pla[mt][kt][half+1] = pack_bf2(
                    __float2bfloat16(e2 - __bfloat162float(h2)),
                    __float2bfloat16(e3 - __bfloat162float(h3)));
            }
        }
        #pragma unroll
        for (int ntc = 0; ntc < 4; ++ntc) {
            const int c = ntc*8 + ld4;
            const uint32_t* vhp = sVhw + c*132 + ch*16 + l4;
            const uint32_t* vlp = sVlw + c*132 + ch*16 + l4;
            uint32_t vh[2][2], vl[2][2];
            vh[0][0]=vhp[0]; vh[0][1]=vhp[4]; vh[1][0]=vhp[8]; vh[1][1]=vhp[12];
            vl[0][0]=vlp[0]; vl[0][1]=vlp[4]; vl[1][0]=vlp[8]; vl[1][1]=vlp[12];
            #pragma unroll
            for (int mt = 0; mt < 2; ++mt) {
                #pragma unroll
                for (int kt = 0; kt < 2; ++kt) {
                    mma16816(acc[mt][ntc], Pha[mt][kt], vh[kt][0], vh[kt][1]);
                    mma16816(acc[mt][ntc], Pha[mt][kt], vl[kt][0], vl[kt][1]);
                    mma16816(acc[mt][ntc], Pla[mt][kt], vh[kt][0], vh[kt][1]);
                }
            }
        }
    }

    #pragma unroll
    for (int mt = 0; mt < 2; ++mt)
    #pragma unroll
    for (int rr = 0; rr < 2; ++rr) {
        float d = dsum[mt][rr];
        d += __shfl_xor_sync(0xffffffffu, d, 1);
        d += __shfl_xor_sync(0xffffffffu, d, 2);
        dsum[mt][rr] = 1.f / d;
    }

    const size_t obase = (size_t)ih * 8192;
    #pragma unroll
    for (int mt = 0; mt < 2; ++mt) {
        const int r0 = m0 + mt*16 + ld4;
        #pragma unroll
        for (int ntc = 0; ntc < 4; ++ntc) {
            const int c0 = ntc*8 + l4*2;
            {
                float2 gv = *(const float2*)(g_gate + obase + r0*32 + c0);
                float2 o;
                o.x = acc[mt][ntc][0] * dsum[mt][0] * gv.x;
                o.y = acc[mt][ntc][1] * dsum[mt][0] * gv.y;
                *(float2*)(g_o + obase + r0*32 + c0) = o;
            }
            {
                float2 gv = *(const float2*)(g_gate + obase + (r0+8)*32 + c0);
                float2 o;
                o.x = acc[mt][ntc][2] * dsum[mt][1] * gv.x;
                o.y = acc[mt][ntc][3] * dsum[mt][1] * gv.y;
                *(float2*)(g_o + obase + (r0+8)*32 + c0) = o;
            }
        }
    }
}

// ---------------------------------------------------------------------------
// Kernel 3: out = o @ Wo.T + bo. Two threads per row (16 outputs each).
// ---------------------------------------------------------------------------
__global__ __launch_bounds__(256) void out_kernel(
    const float* __restrict__ Wo, const float* __restrict__ bo,
    float* __restrict__ out)
{
    __shared__ float sWo[4096];
    __shared__ float sbo[32];
    const int tid = threadIdx.x;
    for (int idx = tid; idx < 4096; idx += 256) sWo[idx] = Wo[idx];
    if (tid < 32) sbo[tid] = bo[tid];
    __syncthreads();

    const int t = blockIdx.x * 256 + tid;   // 0..131071
    const int r = t >> 1, half = t & 1;
    const int i = r >> 8, j = r & 255;

    float ov[128];
    #pragma unroll
    for (int h = 0; h < 4; ++h) {
        const float4* op = (const float4*)(g_o + ((size_t)(i*4 + h)*256 + j)*32);
        #pragma unroll
        for (int c4 = 0; c4 < 8; ++c4) {
            float4 tt = op[c4];
            ov[h*32+c4*4+0]=tt.x; ov[h*32+c4*4+1]=tt.y;
            ov[h*32+c4*4+2]=tt.z; ov[h*32+c4*4+3]=tt.w;
        }
    }
    const int co_base = half * 16;
    #pragma unroll
    for (int co4 = 0; co4 < 4; ++co4) {
        float a[4];
        #pragma unroll
        for (int u = 0; u < 4; ++u) {
            const int co = co_base + co4*4 + u;
            const float4* w4 = (const float4*)(sWo + co*128);
            float t0=0.f,t1=0.f,t2=0.f,t3=0.f;
            #pragma unroll
            for (int c4 = 0; c4 < 32; ++c4) {
                float4 w = w4[c4];
                t0 += ov[c4*4+0]*w.x; t1 += ov[c4*4+1]*w.y;
                t2 += ov[c4*4+2]*w.z; t3 += ov[c4*4+3]*w.w;
            }
            a[u] = sbo[co] + (t0+t1) + (t2+t3);
        }
        *(float4*)(out + (size_t)r*32 + co_base + co4*4) = make_float4(a[0],a[1],a[2],a[3]);
    }
}

// ---------------------------------------------------------------------------
extern "C" void kernel_launch(void* const* d_in, const int* in_sizes, int n_in,
                              void* d_out, int out_size) {
    const float* z    = (const float*)d_in[0];
    const float* ln_g = (const float*)d_in[1];
    const float* ln_b = (const float*)d_in[2];
    const float* Wq   = (const float*)d_in[3];
    const float* Wk   = (const float*)d_in[4];
    const float* Wv   = (const float*)d_in[5];
    // d_in[6] = Wb: bias is constant along the softmax axis -> cancels exactly
    const float* Wg   = (const float*)d_in[7];
    const float* bg   = (const float*)d_in[8];
    const float* Wo   = (const float*)d_in[9];
    const float* bo   = (const float*)d_in[10];
    float* out = (float*)d_out;

    cudaFuncSetAttribute(attn_kernel, cudaFuncAttributeMaxDynamicSharedMemorySize, 110592);

    proj_kernel<<<1024, 256>>>(z, ln_g, ln_b, Wq, Wk, Wv, Wg, bg);
    attn_kernel<<<1024, 256, 107520>>>();
    out_kernel<<<512, 256>>>(Wo, bo, out);
}

// round 11
// speedup vs baseline: 1.2490x; 1.2490x over previous
#include <cuda_runtime.h>
#include <cuda_bf16.h>
#include <stdint.h>
#include <math.h>

#define SCALE_Q 0.17677669529663687f   // 1/sqrt(32)

// Scratch (static __device__; no allocations allowed)
__device__ __nv_bfloat16 g_znhl[65536*64];     // [r][znh(32)|znl(32)]
__device__ __nv_bfloat16 g_qhl[1024*256*64];   // [ih][j][qh(32)|ql(32)] (pre-scaled)
__device__ __nv_bfloat16 g_khl[1024*256*64];   // [ih][j][kh|kl]
__device__ __nv_bfloat16 g_vhl[1024*256*64];   // [ih][j][vh|vl]
__device__ float g_gate[1024*256*32];
__device__ float g_o   [1024*256*32];

__device__ __forceinline__ uint32_t pack_bf2(__nv_bfloat16 a, __nv_bfloat16 b) {
    __nv_bfloat162 t; t.x = a; t.y = b;
    return *reinterpret_cast<uint32_t*>(&t);
}
__device__ __forceinline__ uint32_t split_hi(float a, float b, float* ra, float* rb) {
    __nv_bfloat16 ha = __float2bfloat16(a), hb = __float2bfloat16(b);
    *ra = a - __bfloat162float(ha);
    *rb = b - __bfloat162float(hb);
    return pack_bf2(ha, hb);
}

// m16n8k16 row.col bf16 -> f32 accumulate (sm_80+ PTX, valid on compute_103)
__device__ __forceinline__ void mma16816(float* d, const uint32_t* a,
                                         uint32_t b0, uint32_t b1) {
    asm volatile(
        "mma.sync.aligned.m16n8k16.row.col.f32.bf16.bf16.f32 "
        "{%0,%1,%2,%3}, {%4,%5,%6,%7}, {%8,%9}, {%0,%1,%2,%3};"
        : "+f"(d[0]), "+f"(d[1]), "+f"(d[2]), "+f"(d[3])
        : "r"(a[0]), "r"(a[1]), "r"(a[2]), "r"(a[3]), "r"(b0), "r"(b1));
}

// ---------------------------------------------------------------------------
// Kernel 1a: LayerNorm only -> zn bf16 hi/lo rows
// ---------------------------------------------------------------------------
__global__ __launch_bounds__(256) void ln_kernel(
    const float* __restrict__ z, const float* __restrict__ ln_g,
    const float* __restrict__ ln_b)
{
    __shared__ float sg[32], sb[32];
    const int tid = threadIdx.x;
    if (tid < 32) { sg[tid] = ln_g[tid]; sb[tid] = ln_b[tid]; }
    __syncthreads();

    const int r = blockIdx.x * 256 + tid;
    float x[32];
    const float4* zp = (const float4*)(z + (size_t)r * 32);
    #pragma unroll
    for (int c4 = 0; c4 < 8; ++c4) {
        float4 t = zp[c4];
        x[c4*4+0]=t.x; x[c4*4+1]=t.y; x[c4*4+2]=t.z; x[c4*4+3]=t.w;
    }
    float mu = 0.f;
    #pragma unroll
    for (int c = 0; c < 32; ++c) mu += x[c];
    mu *= (1.f/32.f);
    float var = 0.f;
    #pragma unroll
    for (int c = 0; c < 32; ++c) { float d = x[c]-mu; var += d*d; }
    var *= (1.f/32.f);
    const float inv = rsqrtf(var + 1e-5f);

    __nv_bfloat16* row = g_znhl + (size_t)r * 64;
    #pragma unroll
    for (int c = 0; c < 32; c += 2) {
        float a = (x[c]-mu)*inv*sg[c] + sb[c];
        float b = (x[c+1]-mu)*inv*sg[c+1] + sb[c+1];
        float la, lb;
        uint32_t hi = split_hi(a, b, &la, &lb);
        *(uint32_t*)(row + c)      = hi;
        *(uint32_t*)(row + 32 + c) = pack_bf2(__float2bfloat16(la), __float2bfloat16(lb));
    }
}

// ---------------------------------------------------------------------------
// Kernel 1b: projections as split-bf16 HMMA GEMM.
// CTA = (row-tile of 64, matrix in {q,k,v,g}); 8 warps: 2 M-tiles x 4 N-tiles.
// Weights + A staged in smem with the pitch-36 fragment layout (as attn's K).
// ---------------------------------------------------------------------------
__global__ __launch_bounds__(256) void projmm_kernel(
    const float* __restrict__ Wq, const float* __restrict__ Wk,
    const float* __restrict__ Wv, const float* __restrict__ Wg,
    const float* __restrict__ bg)
{
    __shared__ uint32_t sW[128*36];   // 18432 B
    __shared__ uint32_t sA[64*36];    //  9216 B
    __shared__ float sbg[128];

    const int tid = threadIdx.x;
    const int mat = blockIdx.x & 3;
    const int r0  = (blockIdx.x >> 2) * 64;
    const float* W = (mat == 0) ? Wq : (mat == 1) ? Wk : (mat == 2) ? Wv : Wg;

    // Stage weights: row n = output col, 16 hi words + 16 lo words (k pairs)
    {
        const int row = tid >> 1, half = tid & 1;
        const float4* wp = (const float4*)(W + row*32 + half*16);
        #pragma unroll
        for (int q4 = 0; q4 < 4; ++q4) {
            float4 wv = wp[q4];
            float lx, ly, lz, lw;
            uint32_t h0 = split_hi(wv.x, wv.y, &lx, &ly);
            uint32_t h1 = split_hi(wv.z, wv.w, &lz, &lw);
            const int w0 = half*8 + q4*2;
            sW[row*36 + w0]      = h0;
            sW[row*36 + w0 + 1]  = h1;
            sW[row*36 + 16 + w0]     = pack_bf2(__float2bfloat16(lx), __float2bfloat16(ly));
            sW[row*36 + 16 + w0 + 1] = pack_bf2(__float2bfloat16(lz), __float2bfloat16(lw));
        }
    }
    if (tid < 128) sbg[tid] = bg[tid];
    // Stage A tile (64 rows of zn hi/lo)
    {
        const uint2* ag = (const uint2*)(g_znhl + (size_t)r0 * 64);
        uint2* sA2 = (uint2*)sA;
        for (int x = tid; x < 1024; x += 256) {
            int row = x >> 4, w = x & 15;
            sA2[row*18 + w] = ag[row*16 + w];
        }
    }
    __syncthreads();

    const int warp = tid >> 5, lane = tid & 31;
    const int l4 = lane & 3, ld4 = lane >> 2;
    const int mrow = (warp & 1) * 32;
    const int ncol = (warp >> 1) * 32;

    uint32_t Ah[2][2][4], Al[2][2][4];
    #pragma unroll
    for (int mt = 0; mt < 2; ++mt)
    #pragma unroll
    for (int kt = 0; kt < 2; ++kt) {
        const int r = mrow + mt*16 + ld4;
        const uint32_t* p0 = sA + r*36 + kt*8 + l4;
        const uint32_t* p1 = sA + (r+8)*36 + kt*8 + l4;
        Ah[mt][kt][0] = p0[0];  Ah[mt][kt][1] = p1[0];
        Ah[mt][kt][2] = p0[4];  Ah[mt][kt][3] = p1[4];
        Al[mt][kt][0] = p0[16]; Al[mt][kt][1] = p1[16];
        Al[mt][kt][2] = p0[20]; Al[mt][kt][3] = p1[20];
    }

    const int ig = r0 >> 8;                // whole 64-row tile shares i
    #pragma unroll
    for (int nt = 0; nt < 4; ++nt) {
        const int n = ncol + nt*8 + ld4;
        const uint32_t* wp = sW + n*36 + l4;
        uint32_t bh[2][2], bl[2][2];
        bh[0][0]=wp[0];  bh[0][1]=wp[4];  bh[1][0]=wp[8];  bh[1][1]=wp[12];
        bl[0][0]=wp[16]; bl[0][1]=wp[20]; bl[1][0]=wp[24]; bl[1][1]=wp[28];
        #pragma unroll
        for (int mt = 0; mt < 2; ++mt) {
            float s[4] = {0,0,0,0}, s2[4] = {0,0,0,0};
            mma16816(s,  Ah[mt][0], bh[0][0], bh[0][1]);
            mma16816(s,  Ah[mt][1], bh[1][0], bh[1][1]);
            mma16816(s2, Ah[mt][0], bl[0][0], bl[0][1]);
            mma16816(s2, Ah[mt][1], bl[1][0], bl[1][1]);
            mma16816(s2, Al[mt][0], bh[0][0], bh[0][1]);
            mma16816(s2, Al[mt][1], bh[1][0], bh[1][1]);
            #pragma unroll
            for (int u = 0; u < 4; ++u) s[u] += s2[u];

            const int rg0 = r0 + mrow + mt*16 + ld4;   // rows rg0 and rg0+8
            const int ocol = ncol + nt*8 + l4*2;       // cols ocol, ocol+1
            const int h = ocol >> 5, c = ocol & 31;
            const int j0 = rg0 & 255;
            const size_t base = ((size_t)(ig*4 + h)*256);
            if (mat == 3) {                            // gate
                float* g0 = g_gate + (base + j0)*32;
                float* g1 = g_gate + (base + j0 + 8)*32;
                *(float2*)(g0 + c) = make_float2(
                    1.f/(1.f+__expf(-(s[0]+sbg[ocol]))), 1.f/(1.f+__expf(-(s[1]+sbg[ocol+1]))));
                *(float2*)(g1 + c) = make_float2(
                    1.f/(1.f+__expf(-(s[2]+sbg[ocol]))), 1.f/(1.f+__expf(-(s[3]+sbg[ocol+1]))));
            } else {
                if (mat == 0) {
                    #pragma unroll
                    for (int u = 0; u < 4; ++u) s[u] *= SCALE_Q;
                }
                __nv_bfloat16* dst = (mat == 0) ? g_qhl : (mat == 1) ? g_khl : g_vhl;
                __nv_bfloat16* d0 = dst + (base + j0)*64;
                __nv_bfloat16* d1 = dst + (base + j0 + 8)*64;
                float la, lb;
                uint32_t hi0 = split_hi(s[0], s[1], &la, &lb);
                *(uint32_t*)(d0 + c)      = hi0;
                *(uint32_t*)(d0 + 32 + c) = pack_bf2(__float2bfloat16(la), __float2bfloat16(lb));
                uint32_t hi1 = split_hi(s[2], s[3], &la, &lb);
                *(uint32_t*)(d1 + c)      = hi1;
                *(uint32_t*)(d1 + 32 + c) = pack_bf2(__float2bfloat16(la), __float2bfloat16(lb));
            }
        }
    }
}

// ---------------------------------------------------------------------------
// Kernel 2: HMMA attention. One CTA per (i,h); 8 warps x 32 query rows.
// Q fragments LDG'd directly from global (no sQ staging): smem 107KB -> 69KB.
// S computed as two independent MMA chains (ILP) then added.
// ---------------------------------------------------------------------------
__global__ __launch_bounds__(256) void attn_kernel()
{
    extern __shared__ __align__(16) char smem[];
    uint32_t* sK = (uint32_t*)smem;                       // 256*36 words = 36864 B
    __nv_bfloat16* sVh = (__nv_bfloat16*)(sK + 256*36);   // 32*264*2 = 16896 B
    __nv_bfloat16* sVl = sVh + 32*264;                    // 16896 B

    const int tid = threadIdx.x;
    const int ih = blockIdx.x;
    const int warp = tid >> 5, lane = tid & 31;
    const int l4 = lane & 3, ld4 = lane >> 2;
    const int m0 = warp * 32;

    // Q fragments straight from global (registers only; overlaps staging)
    uint32_t Qh[2][2][4], Ql[2][2][4];
    {
        const uint32_t* qgw = (const uint32_t*)(g_qhl + (size_t)ih*16384);
        #pragma unroll
        for (int mt = 0; mt < 2; ++mt)
        #pragma unroll
        for (int kt = 0; kt < 2; ++kt) {
            const int r = m0 + mt*16 + ld4;
            const uint32_t* p0 = qgw + r*32 + kt*8 + l4;
            const uint32_t* p1 = qgw + (r+8)*32 + kt*8 + l4;
            Qh[mt][kt][0] = p0[0];  Qh[mt][kt][1] = p1[0];
            Qh[mt][kt][2] = p0[4];  Qh[mt][kt][3] = p1[4];
            Ql[mt][kt][0] = p0[16]; Ql[mt][kt][1] = p1[16];
            Ql[mt][kt][2] = p0[20]; Ql[mt][kt][3] = p1[20];
        }
    }
    // Stage K rows (full row = 16 uint2)
    {
        const uint2* kg = (const uint2*)(g_khl + (size_t)ih*16384);
        uint2* sK2 = (uint2*)sK;
        for (int x = tid; x < 4096; x += 256) {
            int row = x >> 4, w = x & 15;
            sK2[row*18 + w] = kg[x];
        }
    }
    // Stage V transposed: thread j handles row j
    {
        const uint4* vg = (const uint4*)(g_vhl + (size_t)ih*16384) + tid*8;
        uint32_t vb[32];
        #pragma unroll
        for (int t = 0; t < 8; ++t) {
            uint4 u = vg[t];
            vb[t*4+0]=u.x; vb[t*4+1]=u.y; vb[t*4+2]=u.z; vb[t*4+3]=u.w;
        }
        const __nv_bfloat16* vbh = (const __nv_bfloat16*)vb;
        #pragma unroll
        for (int c = 0; c < 32; ++c) {
            sVh[c*264 + tid] = vbh[c];
            sVl[c*264 + tid] = vbh[32 + c];
        }
    }
    __syncthreads();

    float acc[2][4][4];
    #pragma unroll
    for (int mt = 0; mt < 2; ++mt)
    #pragma unroll
    for (int nt = 0; nt < 4; ++nt)
    #pragma unroll
    for (int u = 0; u < 4; ++u) acc[mt][nt][u] = 0.f;
    float dsum[2][2] = {{0.f,0.f},{0.f,0.f}};

    const uint32_t* sVhw = (const uint32_t*)sVh;
    const uint32_t* sVlw = (const uint32_t*)sVl;

    for (int ch = 0; ch < 8; ++ch) {
        uint32_t Pha[2][2][4], Pla[2][2][4];
        #pragma unroll
        for (int nt = 0; nt < 4; ++nt) {
            const int n = ch*32 + nt*8 + ld4;
            const uint32_t* kp = sK + n*36 + l4;
            uint32_t bh[2][2], bl[2][2];
            bh[0][0]=kp[0];  bh[0][1]=kp[4];  bh[1][0]=kp[8];  bh[1][1]=kp[12];
            bl[0][0]=kp[16]; bl[0][1]=kp[20]; bl[1][0]=kp[24]; bl[1][1]=kp[28];
            #pragma unroll
            for (int mt = 0; mt < 2; ++mt) {
                float s[4] = {0,0,0,0}, s2[4] = {0,0,0,0};
                mma16816(s,  Qh[mt][0], bh[0][0], bh[0][1]);
                mma16816(s,  Qh[mt][1], bh[1][0], bh[1][1]);
                mma16816(s2, Qh[mt][0], bl[0][0], bl[0][1]);
                mma16816(s2, Qh[mt][1], bl[1][0], bl[1][1]);
                mma16816(s2, Ql[mt][0], bh[0][0], bh[0][1]);
                mma16816(s2, Ql[mt][1], bh[1][0], bh[1][1]);
                const float e0 = __expf(s[0]+s2[0]), e1 = __expf(s[1]+s2[1]);
                const float e2 = __expf(s[2]+s2[2]), e3 = __expf(s[3]+s2[3]);
                dsum[mt][0] += e0 + e1;
                dsum[mt][1] += e2 + e3;
                float l0, l1, l2, l3;
                uint32_t h01 = split_hi(e0, e1, &l0, &l1);
                uint32_t h23 = split_hi(e2, e3, &l2, &l3);
                const int kt = nt >> 1, half = (nt & 1) * 2;
                Pha[mt][kt][half+0] = h01;
                Pha[mt][kt][half+1] = h23;
                Pla[mt][kt][half+0] = pack_bf2(__float2bfloat16(l0), __float2bfloat16(l1));
                Pla[mt][kt][half+1] = pack_bf2(__float2bfloat16(l2), __float2bfloat16(l3));
            }
        }
        #pragma unroll
        for (int ntc = 0; ntc < 4; ++ntc) {
            const int c = ntc*8 + ld4;
            const uint32_t* vhp = sVhw + c*132 + ch*16 + l4;
            const uint32_t* vlp = sVlw + c*132 + ch*16 + l4;
            uint32_t vh[2][2], vl[2][2];
            vh[0][0]=vhp[0]; vh[0][1]=vhp[4]; vh[1][0]=vhp[8]; vh[1][1]=vhp[12];
            vl[0][0]=vlp[0]; vl[0][1]=vlp[4]; vl[1][0]=vlp[8]; vl[1][1]=vlp[12];
            #pragma unroll
            for (int mt = 0; mt < 2; ++mt) {
                #pragma unroll
                for (int kt = 0; kt < 2; ++kt) {
                    mma16816(acc[mt][ntc], Pha[mt][kt], vh[kt][0], vh[kt][1]);
                    mma16816(acc[mt][ntc], Pha[mt][kt], vl[kt][0], vl[kt][1]);
                    mma16816(acc[mt][ntc], Pla[mt][kt], vh[kt][0], vh[kt][1]);
                }
            }
        }
    }

    #pragma unroll
    for (int mt = 0; mt < 2; ++mt)
    #pragma unroll
    for (int rr = 0; rr < 2; ++rr) {
        float d = dsum[mt][rr];
        d += __shfl_xor_sync(0xffffffffu, d, 1);
        d += __shfl_xor_sync(0xffffffffu, d, 2);
        dsum[mt][rr] = 1.f / d;
    }

    const size_t obase = (size_t)ih * 8192;
    #pragma unroll
    for (int mt = 0; mt < 2; ++mt) {
        const int r0 = m0 + mt*16 + ld4;
        #pragma unroll
        for (int ntc = 0; ntc < 4; ++ntc) {
            const int c0 = ntc*8 + l4*2;
            {
                float2 gv = *(const float2*)(g_gate + obase + r0*32 + c0);
                float2 o;
                o.x = acc[mt][ntc][0] * dsum[mt][0] * gv.x;
                o.y = acc[mt][ntc][1] * dsum[mt][0] * gv.y;
                *(float2*)(g_o + obase + r0*32 + c0) = o;
            }
            {
                float2 gv = *(const float2*)(g_gate + obase + (r0+8)*32 + c0);
                float2 o;
                o.x = acc[mt][ntc][2] * dsum[mt][1] * gv.x;
                o.y = acc[mt][ntc][3] * dsum[mt][1] * gv.y;
                *(float2*)(g_o + obase + (r0+8)*32 + c0) = o;
            }
        }
    }
}

// ---------------------------------------------------------------------------
// Kernel 3: out = o @ Wo.T + bo. Two threads per row (16 outputs each).
// ---------------------------------------------------------------------------
__global__ __launch_bounds__(256) void out_kernel(
    const float* __restrict__ Wo, const float* __restrict__ bo,
    float* __restrict__ out)
{
    __shared__ float sWo[4096];
    __shared__ float sbo[32];
    const int tid = threadIdx.x;
    for (int idx = tid; idx < 4096; idx += 256) sWo[idx] = Wo[idx];
    if (tid < 32) sbo[tid] = bo[tid];
    __syncthreads();

    const int t = blockIdx.x * 256 + tid;   // 0..131071
    const int r = t >> 1, half = t & 1;
    const int i = r >> 8, j = r & 255;

    float ov[128];
    #pragma unroll
    for (int h = 0; h < 4; ++h) {
        const float4* op = (const float4*)(g_o + ((size_t)(i*4 + h)*256 + j)*32);
        #pragma unroll
        for (int c4 = 0; c4 < 8; ++c4) {
            float4 tt = op[c4];
            ov[h*32+c4*4+0]=tt.x; ov[h*32+c4*4+1]=tt.y;
            ov[h*32+c4*4+2]=tt.z; ov[h*32+c4*4+3]=tt.w;
        }
    }
    const int co_base = half * 16;
    #pragma unroll
    for (int co4 = 0; co4 < 4; ++co4) {
        float a[4];
        #pragma unroll
        for (int u = 0; u < 4; ++u) {
            const int co = co_base + co4*4 + u;
            const float4* w4 = (const float4*)(sWo + co*128);
            float t0=0.f,t1=0.f,t2=0.f,t3=0.f;
            #pragma unroll
            for (int c4 = 0; c4 < 32; ++c4) {
                float4 w = w4[c4];
                t0 += ov[c4*4+0]*w.x; t1 += ov[c4*4+1]*w.y;
                t2 += ov[c4*4+2]*w.z; t3 += ov[c4*4+3]*w.w;
            }
            a[u] = sbo[co] + (t0+t1) + (t2+t3);
        }
        *(float4*)(out + (size_t)r*32 + co_base + co4*4) = make_float4(a[0],a[1],a[2],a[3]);
    }
}

// ---------------------------------------------------------------------------
extern "C" void kernel_launch(void* const* d_in, const int* in_sizes, int n_in,
                              void* d_out, int out_size) {
    const float* z    = (const float*)d_in[0];
    const float* ln_g = (const float*)d_in[1];
    const float* ln_b = (const float*)d_in[2];
    const float* Wq   = (const float*)d_in[3];
    const float* Wk   = (const float*)d_in[4];
    const float* Wv   = (const float*)d_in[5];
    // d_in[6] = Wb: bias is constant along the softmax axis -> cancels exactly
    const float* Wg   = (const float*)d_in[7];
    const float* bg   = (const float*)d_in[8];
    const float* Wo   = (const float*)d_in[9];
    const float* bo   = (const float*)d_in[10];
    float* out = (float*)d_out;

    cudaFuncSetAttribute(attn_kernel, cudaFuncAttributeMaxDynamicSharedMemorySize, 70656);

    ln_kernel<<<256, 256>>>(z, ln_g, ln_b);
    projmm_kernel<<<4096, 256>>>(Wq, Wk, Wv, Wg, bg);
    attn_kernel<<<1024, 256, 70656>>>();
    out_kernel<<<512, 256>>>(Wo, bo, out);
}

// round 12
// speedup vs baseline: 1.4021x; 1.1226x over previous
#include <cuda_runtime.h>
#include <cuda_bf16.h>
#include <stdint.h>
#include <math.h>

#define SCALE_Q 0.17677669529663687f   // 1/sqrt(32)

// Scratch (static __device__; no allocations allowed)
__device__ __nv_bfloat16 g_znhl[65536*64];     // [r][znh(32)|znl(32)]
__device__ __nv_bfloat16 g_qhl[1024*256*64];   // [ih][j][qh(32)|ql(32)] (pre-scaled)
__device__ __nv_bfloat16 g_khl[1024*256*64];   // [ih][j][kh|kl]
__device__ __nv_bfloat16 g_vhl[1024*256*64];   // [ih][j][vh|vl]
__device__ float g_gate[1024*256*32];
__device__ __nv_bfloat16 g_ohl[65536*256];     // [r][oh(128)|ol(128)], col = h*32+c

__device__ __forceinline__ uint32_t pack_bf2(__nv_bfloat16 a, __nv_bfloat16 b) {
    __nv_bfloat162 t; t.x = a; t.y = b;
    return *reinterpret_cast<uint32_t*>(&t);
}
__device__ __forceinline__ uint32_t split_hi(float a, float b, float* ra, float* rb) {
    __nv_bfloat16 ha = __float2bfloat16(a), hb = __float2bfloat16(b);
    *ra = a - __bfloat162float(ha);
    *rb = b - __bfloat162float(hb);
    return pack_bf2(ha, hb);
}

// m16n8k16 row.col bf16 -> f32 accumulate (sm_80+ PTX, valid on compute_103)
__device__ __forceinline__ void mma16816(float* d, const uint32_t* a,
                                         uint32_t b0, uint32_t b1) {
    asm volatile(
        "mma.sync.aligned.m16n8k16.row.col.f32.bf16.bf16.f32 "
        "{%0,%1,%2,%3}, {%4,%5,%6,%7}, {%8,%9}, {%0,%1,%2,%3};"
        : "+f"(d[0]), "+f"(d[1]), "+f"(d[2]), "+f"(d[3])
        : "r"(a[0]), "r"(a[1]), "r"(a[2]), "r"(a[3]), "r"(b0), "r"(b1));
}

// ---------------------------------------------------------------------------
// Kernel 1a: LayerNorm only -> zn bf16 hi/lo rows
// ---------------------------------------------------------------------------
__global__ __launch_bounds__(256) void ln_kernel(
    const float* __restrict__ z, const float* __restrict__ ln_g,
    const float* __restrict__ ln_b)
{
    __shared__ float sg[32], sb[32];
    const int tid = threadIdx.x;
    if (tid < 32) { sg[tid] = ln_g[tid]; sb[tid] = ln_b[tid]; }
    __syncthreads();

    const int r = blockIdx.x * 256 + tid;
    float x[32];
    const float4* zp = (const float4*)(z + (size_t)r * 32);
    #pragma unroll
    for (int c4 = 0; c4 < 8; ++c4) {
        float4 t = zp[c4];
        x[c4*4+0]=t.x; x[c4*4+1]=t.y; x[c4*4+2]=t.z; x[c4*4+3]=t.w;
    }
    float mu = 0.f;
    #pragma unroll
    for (int c = 0; c < 32; ++c) mu += x[c];
    mu *= (1.f/32.f);
    float var = 0.f;
    #pragma unroll
    for (int c = 0; c < 32; ++c) { float d = x[c]-mu; var += d*d; }
    var *= (1.f/32.f);
    const float inv = rsqrtf(var + 1e-5f);

    __nv_bfloat16* row = g_znhl + (size_t)r * 64;
    #pragma unroll
    for (int c = 0; c < 32; c += 2) {
        float a = (x[c]-mu)*inv*sg[c] + sb[c];
        float b = (x[c+1]-mu)*inv*sg[c+1] + sb[c+1];
        float la, lb;
        uint32_t hi = split_hi(a, b, &la, &lb);
        *(uint32_t*)(row + c)      = hi;
        *(uint32_t*)(row + 32 + c) = pack_bf2(__float2bfloat16(la), __float2bfloat16(lb));
    }
}

// ---------------------------------------------------------------------------
// Kernel 1b: projections as split-bf16 HMMA GEMM. (unchanged from R11)
// ---------------------------------------------------------------------------
__global__ __launch_bounds__(256) void projmm_kernel(
    const float* __restrict__ Wq, const float* __restrict__ Wk,
    const float* __restrict__ Wv, const float* __restrict__ Wg,
    const float* __restrict__ bg)
{
    __shared__ uint32_t sW[128*36];
    __shared__ uint32_t sA[64*36];
    __shared__ float sbg[128];

    const int tid = threadIdx.x;
    const int mat = blockIdx.x & 3;
    const int r0  = (blockIdx.x >> 2) * 64;
    const float* W = (mat == 0) ? Wq : (mat == 1) ? Wk : (mat == 2) ? Wv : Wg;

    {
        const int row = tid >> 1, half = tid & 1;
        const float4* wp = (const float4*)(W + row*32 + half*16);
        #pragma unroll
        for (int q4 = 0; q4 < 4; ++q4) {
            float4 wv = wp[q4];
            float lx, ly, lz, lw;
            uint32_t h0 = split_hi(wv.x, wv.y, &lx, &ly);
            uint32_t h1 = split_hi(wv.z, wv.w, &lz, &lw);
            const int w0 = half*8 + q4*2;
            sW[row*36 + w0]      = h0;
            sW[row*36 + w0 + 1]  = h1;
            sW[row*36 + 16 + w0]     = pack_bf2(__float2bfloat16(lx), __float2bfloat16(ly));
            sW[row*36 + 16 + w0 + 1] = pack_bf2(__float2bfloat16(lz), __float2bfloat16(lw));
        }
    }
    if (tid < 128) sbg[tid] = bg[tid];
    {
        const uint2* ag = (const uint2*)(g_znhl + (size_t)r0 * 64);
        uint2* sA2 = (uint2*)sA;
        for (int x = tid; x < 1024; x += 256) {
            int row = x >> 4, w = x & 15;
            sA2[row*18 + w] = ag[row*16 + w];
        }
    }
    __syncthreads();

    const int warp = tid >> 5, lane = tid & 31;
    const int l4 = lane & 3, ld4 = lane >> 2;
    const int mrow = (warp & 1) * 32;
    const int ncol = (warp >> 1) * 32;

    uint32_t Ah[2][2][4], Al[2][2][4];
    #pragma unroll
    for (int mt = 0; mt < 2; ++mt)
    #pragma unroll
    for (int kt = 0; kt < 2; ++kt) {
        const int r = mrow + mt*16 + ld4;
        const uint32_t* p0 = sA + r*36 + kt*8 + l4;
        const uint32_t* p1 = sA + (r+8)*36 + kt*8 + l4;
        Ah[mt][kt][0] = p0[0];  Ah[mt][kt][1] = p1[0];
        Ah[mt][kt][2] = p0[4];  Ah[mt][kt][3] = p1[4];
        Al[mt][kt][0] = p0[16]; Al[mt][kt][1] = p1[16];
        Al[mt][kt][2] = p0[20]; Al[mt][kt][3] = p1[20];
    }

    const int ig = r0 >> 8;
    #pragma unroll
    for (int nt = 0; nt < 4; ++nt) {
        const int n = ncol + nt*8 + ld4;
        const uint32_t* wp = sW + n*36 + l4;
        uint32_t bh[2][2], bl[2][2];
        bh[0][0]=wp[0];  bh[0][1]=wp[4];  bh[1][0]=wp[8];  bh[1][1]=wp[12];
        bl[0][0]=wp[16]; bl[0][1]=wp[20]; bl[1][0]=wp[24]; bl[1][1]=wp[28];
        #pragma unroll
        for (int mt = 0; mt < 2; ++mt) {
            float s[4] = {0,0,0,0}, s2[4] = {0,0,0,0};
            mma16816(s,  Ah[mt][0], bh[0][0], bh[0][1]);
            mma16816(s,  Ah[mt][1], bh[1][0], bh[1][1]);
            mma16816(s2, Ah[mt][0], bl[0][0], bl[0][1]);
            mma16816(s2, Ah[mt][1], bl[1][0], bl[1][1]);
            mma16816(s2, Al[mt][0], bh[0][0], bh[0][1]);
            mma16816(s2, Al[mt][1], bh[1][0], bh[1][1]);
            #pragma unroll
            for (int u = 0; u < 4; ++u) s[u] += s2[u];

            const int rg0 = r0 + mrow + mt*16 + ld4;
            const int ocol = ncol + nt*8 + l4*2;
            const int h = ocol >> 5, c = ocol & 31;
            const int j0 = rg0 & 255;
            const size_t base = ((size_t)(ig*4 + h)*256);
            if (mat == 3) {
                float* g0 = g_gate + (base + j0)*32;
                float* g1 = g_gate + (base + j0 + 8)*32;
                *(float2*)(g0 + c) = make_float2(
                    1.f/(1.f+__expf(-(s[0]+sbg[ocol]))), 1.f/(1.f+__expf(-(s[1]+sbg[ocol+1]))));
                *(float2*)(g1 + c) = make_float2(
                    1.f/(1.f+__expf(-(s[2]+sbg[ocol]))), 1.f/(1.f+__expf(-(s[3]+sbg[ocol+1]))));
            } else {
                if (mat == 0) {
                    #pragma unroll
                    for (int u = 0; u < 4; ++u) s[u] *= SCALE_Q;
                }
                __nv_bfloat16* dst = (mat == 0) ? g_qhl : (mat == 1) ? g_khl : g_vhl;
                __nv_bfloat16* d0 = dst + (base + j0)*64;
                __nv_bfloat16* d1 = dst + (base + j0 + 8)*64;
                float la, lb;
                uint32_t hi0 = split_hi(s[0], s[1], &la, &lb);
                *(uint32_t*)(d0 + c)      = hi0;
                *(uint32_t*)(d0 + 32 + c) = pack_bf2(__float2bfloat16(la), __float2bfloat16(lb));
                uint32_t hi1 = split_hi(s[2], s[3], &la, &lb);
                *(uint32_t*)(d1 + c)      = hi1;
                *(uint32_t*)(d1 + 32 + c) = pack_bf2(__float2bfloat16(la), __float2bfloat16(lb));
            }
        }
    }
}

// ---------------------------------------------------------------------------
// Kernel 2: HMMA attention (body unchanged from R11).
// Epilogue now writes gated o as bf16 hi/lo into g_ohl [r][h*32+c].
// ---------------------------------------------------------------------------
__global__ __launch_bounds__(256) void attn_kernel()
{
    extern __shared__ __align__(16) char smem[];
    uint32_t* sK = (uint32_t*)smem;                       // 36864 B
    __nv_bfloat16* sVh = (__nv_bfloat16*)(sK + 256*36);   // 16896 B
    __nv_bfloat16* sVl = sVh + 32*264;                    // 16896 B

    const int tid = threadIdx.x;
    const int ih = blockIdx.x;
    const int warp = tid >> 5, lane = tid & 31;
    const int l4 = lane & 3, ld4 = lane >> 2;
    const int m0 = warp * 32;

    uint32_t Qh[2][2][4], Ql[2][2][4];
    {
        const uint32_t* qgw = (const uint32_t*)(g_qhl + (size_t)ih*16384);
        #pragma unroll
        for (int mt = 0; mt < 2; ++mt)
        #pragma unroll
        for (int kt = 0; kt < 2; ++kt) {
            const int r = m0 + mt*16 + ld4;
            const uint32_t* p0 = qgw + r*32 + kt*8 + l4;
            const uint32_t* p1 = qgw + (r+8)*32 + kt*8 + l4;
            Qh[mt][kt][0] = p0[0];  Qh[mt][kt][1] = p1[0];
            Qh[mt][kt][2] = p0[4];  Qh[mt][kt][3] = p1[4];
            Ql[mt][kt][0] = p0[16]; Ql[mt][kt][1] = p1[16];
            Ql[mt][kt][2] = p0[20]; Ql[mt][kt][3] = p1[20];
        }
    }
    {
        const uint2* kg = (const uint2*)(g_khl + (size_t)ih*16384);
        uint2* sK2 = (uint2*)sK;
        for (int x = tid; x < 4096; x += 256) {
            int row = x >> 4, w = x & 15;
            sK2[row*18 + w] = kg[x];
        }
    }
    {
        const uint4* vg = (const uint4*)(g_vhl + (size_t)ih*16384) + tid*8;
        uint32_t vb[32];
        #pragma unroll
        for (int t = 0; t < 8; ++t) {
            uint4 u = vg[t];
            vb[t*4+0]=u.x; vb[t*4+1]=u.y; vb[t*4+2]=u.z; vb[t*4+3]=u.w;
        }
        const __nv_bfloat16* vbh = (const __nv_bfloat16*)vb;
        #pragma unroll
        for (int c = 0; c < 32; ++c) {
            sVh[c*264 + tid] = vbh[c];
            sVl[c*264 + tid] = vbh[32 + c];
        }
    }
    __syncthreads();

    float acc[2][4][4];
    #pragma unroll
    for (int mt = 0; mt < 2; ++mt)
    #pragma unroll
    for (int nt = 0; nt < 4; ++nt)
    #pragma unroll
    for (int u = 0; u < 4; ++u) acc[mt][nt][u] = 0.f;
    float dsum[2][2] = {{0.f,0.f},{0.f,0.f}};

    const uint32_t* sVhw = (const uint32_t*)sVh;
    const uint32_t* sVlw = (const uint32_t*)sVl;

    for (int ch = 0; ch < 8; ++ch) {
        uint32_t Pha[2][2][4], Pla[2][2][4];
        #pragma unroll
        for (int nt = 0; nt < 4; ++nt) {
            const int n = ch*32 + nt*8 + ld4;
            const uint32_t* kp = sK + n*36 + l4;
            uint32_t bh[2][2], bl[2][2];
            bh[0][0]=kp[0];  bh[0][1]=kp[4];  bh[1][0]=kp[8];  bh[1][1]=kp[12];
            bl[0][0]=kp[16]; bl[0][1]=kp[20]; bl[1][0]=kp[24]; bl[1][1]=kp[28];
            #pragma unroll
            for (int mt = 0; mt < 2; ++mt) {
                float s[4] = {0,0,0,0}, s2[4] = {0,0,0,0};
                mma16816(s,  Qh[mt][0], bh[0][0], bh[0][1]);
                mma16816(s,  Qh[mt][1], bh[1][0], bh[1][1]);
                mma16816(s2, Qh[mt][0], bl[0][0], bl[0][1]);
                mma16816(s2, Qh[mt][1], bl[1][0], bl[1][1]);
                mma16816(s2, Ql[mt][0], bh[0][0], bh[0][1]);
                mma16816(s2, Ql[mt][1], bh[1][0], bh[1][1]);
                const float e0 = __expf(s[0]+s2[0]), e1 = __expf(s[1]+s2[1]);
                const float e2 = __expf(s[2]+s2[2]), e3 = __expf(s[3]+s2[3]);
                dsum[mt][0] += e0 + e1;
                dsum[mt][1] += e2 + e3;
                float l0, l1, l2, l3;
                uint32_t h01 = split_hi(e0, e1, &l0, &l1);
                uint32_t h23 = split_hi(e2, e3, &l2, &l3);
                const int kt = nt >> 1, half = (nt & 1) * 2;
                Pha[mt][kt][half+0] = h01;
                Pha[mt][kt][half+1] = h23;
                Pla[mt][kt][half+0] = pack_bf2(__float2bfloat16(l0), __float2bfloat16(l1));
                Pla[mt][kt][half+1] = pack_bf2(__float2bfloat16(l2), __float2bfloat16(l3));
            }
        }
        #pragma unroll
        for (int ntc = 0; ntc < 4; ++ntc) {
            const int c = ntc*8 + ld4;
            const uint32_t* vhp = sVhw + c*132 + ch*16 + l4;
            const uint32_t* vlp = sVlw + c*132 + ch*16 + l4;
            uint32_t vh[2][2], vl[2][2];
            vh[0][0]=vhp[0]; vh[0][1]=vhp[4]; vh[1][0]=vhp[8]; vh[1][1]=vhp[12];
            vl[0][0]=vlp[0]; vl[0][1]=vlp[4]; vl[1][0]=vlp[8]; vl[1][1]=vlp[12];
            #pragma unroll
            for (int mt = 0; mt < 2; ++mt) {
                #pragma unroll
                for (int kt = 0; kt < 2; ++kt) {
                    mma16816(acc[mt][ntc], Pha[mt][kt], vh[kt][0], vh[kt][1]);
                    mma16816(acc[mt][ntc], Pha[mt][kt], vl[kt][0], vl[kt][1]);
                    mma16816(acc[mt][ntc], Pla[mt][kt], vh[kt][0], vh[kt][1]);
                }
            }
        }
    }

    #pragma unroll
    for (int mt = 0; mt < 2; ++mt)
    #pragma unroll
    for (int rr = 0; rr < 2; ++rr) {
        float d = dsum[mt][rr];
        d += __shfl_xor_sync(0xffffffffu, d, 1);
        d += __shfl_xor_sync(0xffffffffu, d, 2);
        dsum[mt][rr] = 1.f / d;
    }

    // Epilogue: normalize, gate, split bf16 hi/lo -> g_ohl [r][128 | 128]
    const int rbase = (ih >> 2) * 256;       // global row base (i*256)
    const int cbase = (ih & 3) * 32;         // column base (h*32)
    const size_t gbase = (size_t)ih * 8192;  // g_gate layout unchanged
    uint32_t* ow = (uint32_t*)g_ohl;         // 128 words per row
    #pragma unroll
    for (int mt = 0; mt < 2; ++mt) {
        const int q0 = m0 + mt*16 + ld4;
        #pragma unroll
        for (int ntc = 0; ntc < 4; ++ntc) {
            const int c0 = ntc*8 + l4*2;
            const int wcol = (cbase + c0) >> 1;   // word index of hi pair
            {
                float2 gv = *(const float2*)(g_gate + gbase + q0*32 + c0);
                float o0 = acc[mt][ntc][0] * dsum[mt][0] * gv.x;
                float o1 = acc[mt][ntc][1] * dsum[mt][0] * gv.y;
                float l0, l1;
                uint32_t hi = split_hi(o0, o1, &l0, &l1);
                uint32_t* base = ow + (size_t)(rbase + q0) * 128 + wcol;
                base[0]  = hi;
                base[64] = pack_bf2(__float2bfloat16(l0), __float2bfloat16(l1));
            }
            {
                float2 gv = *(const float2*)(g_gate + gbase + (q0+8)*32 + c0);
                float o0 = acc[mt][ntc][2] * dsum[mt][1] * gv.x;
                float o1 = acc[mt][ntc][3] * dsum[mt][1] * gv.y;
                float l0, l1;
                uint32_t hi = split_hi(o0, o1, &l0, &l1);
                uint32_t* base = ow + (size_t)(rbase + q0 + 8) * 128 + wcol;
                base[0]  = hi;
                base[64] = pack_bf2(__float2bfloat16(l0), __float2bfloat16(l1));
            }
        }
    }
}

// ---------------------------------------------------------------------------
// Kernel 3: out = o @ Wo.T + bo as split-bf16 HMMA GEMM.
// CTA = 256-row tile; 8 warps x 32 rows; N=32, K=128 (4 k-chunks of 32).
// Wo staged hi/lo at pitch 132 (132 mod 32 = 4 -> conflict-free frag loads);
// A fragments LDG'd directly from g_ohl (each element read once).
// ---------------------------------------------------------------------------
__global__ __launch_bounds__(256) void outmm_kernel(
    const float* __restrict__ Wo, const float* __restrict__ bo,
    float* __restrict__ out)
{
    __shared__ uint32_t sW[32*132];   // 16896 B
    __shared__ float sbo[32];
    const int tid = threadIdx.x;
    {
        const int row = tid >> 3, seg = tid & 7;   // 32 rows x 8 segs of 16 floats
        const float4* wp = (const float4*)(Wo + row*128 + seg*16);
        #pragma unroll
        for (int q4 = 0; q4 < 4; ++q4) {
            float4 w = wp[q4];
            float lx, ly, lz, lw;
            uint32_t h0 = split_hi(w.x, w.y, &lx, &ly);
            uint32_t h1 = split_hi(w.z, w.w, &lz, &lw);
            const int w0 = seg*8 + q4*2;
            sW[row*132 + w0]          = h0;
            sW[row*132 + w0 + 1]      = h1;
            sW[row*132 + 64 + w0]     = pack_bf2(__float2bfloat16(lx), __float2bfloat16(ly));
            sW[row*132 + 64 + w0 + 1] = pack_bf2(__float2bfloat16(lz), __float2bfloat16(lw));
        }
    }
    if (tid < 32) sbo[tid] = bo[tid];
    __syncthreads();

    const int warp = tid >> 5, lane = tid & 31;
    const int l4 = lane & 3, ld4 = lane >> 2;
    const int m0 = blockIdx.x * 256 + warp * 32;

    float acc[2][4][4];
    #pragma unroll
    for (int mt = 0; mt < 2; ++mt)
    #pragma unroll
    for (int nt = 0; nt < 4; ++nt)
    #pragma unroll
    for (int u = 0; u < 4; ++u) acc[mt][nt][u] = 0.f;

    const uint32_t* A = (const uint32_t*)g_ohl;  // 128 words/row: 64 hi + 64 lo

    #pragma unroll
    for (int kc = 0; kc < 4; ++kc) {             // k-chunks of 32
        uint32_t Ah[2][2][4], Al[2][2][4];
        #pragma unroll
        for (int mt = 0; mt < 2; ++mt)
        #pragma unroll
        for (int kt = 0; kt < 2; ++kt) {
            const uint32_t* p0 = A + (size_t)(m0 + mt*16 + ld4) * 128 + kc*16 + kt*8 + l4;
            const uint32_t* p1 = p0 + 8*128;
            Ah[mt][kt][0] = p0[0];  Ah[mt][kt][1] = p1[0];
            Ah[mt][kt][2] = p0[4];  Ah[mt][kt][3] = p1[4];
            Al[mt][kt][0] = p0[64]; Al[mt][kt][1] = p1[64];
            Al[mt][kt][2] = p0[68]; Al[mt][kt][3] = p1[68];
        }
        #pragma unroll
        for (int nt = 0; nt < 4; ++nt) {
            const uint32_t* wp = sW + (nt*8 + ld4)*132 + kc*16 + l4;
            uint32_t bh[2][2], bl[2][2];
            bh[0][0]=wp[0];  bh[0][1]=wp[4];  bh[1][0]=wp[8];  bh[1][1]=wp[12];
            bl[0][0]=wp[64]; bl[0][1]=wp[68]; bl[1][0]=wp[72]; bl[1][1]=wp[76];
            #pragma unroll
            for (int mt = 0; mt < 2; ++mt) {
                #pragma unroll
                for (int kt = 0; kt < 2; ++kt) {
                    mma16816(acc[mt][nt], Ah[mt][kt], bh[kt][0], bh[kt][1]);
                    mma16816(acc[mt][nt], Ah[mt][kt], bl[kt][0], bl[kt][1]);
                    mma16816(acc[mt][nt], Al[mt][kt], bh[kt][0], bh[kt][1]);
                }
            }
        }
    }

    #pragma unroll
    for (int mt = 0; mt < 2; ++mt) {
        const int r0 = m0 + mt*16 + ld4;
        #pragma unroll
        for (int nt = 0; nt < 4; ++nt) {
            const int c0 = nt*8 + l4*2;
            *(float2*)(out + (size_t)r0*32 + c0) =
                make_float2(acc[mt][nt][0] + sbo[c0], acc[mt][nt][1] + sbo[c0+1]);
            *(float2*)(out + (size_t)(r0+8)*32 + c0) =
                make_float2(acc[mt][nt][2] + sbo[c0], acc[mt][nt][3] + sbo[c0+1]);
        }
    }
}

// ---------------------------------------------------------------------------
extern "C" void kernel_launch(void* const* d_in, const int* in_sizes, int n_in,
                              void* d_out, int out_size) {
    const float* z    = (const float*)d_in[0];
    const float* ln_g = (const float*)d_in[1];
    const float* ln_b = (const float*)d_in[2];
    const float* Wq   = (const float*)d_in[3];
    const float* Wk   = (const float*)d_in[4];
    const float* Wv   = (const float*)d_in[5];
    // d_in[6] = Wb: bias is constant along the softmax axis -> cancels exactly
    const float* Wg   = (const float*)d_in[7];
    const float* bg   = (const float*)d_in[8];
    const float* Wo   = (const float*)d_in[9];
    const float* bo   = (const float*)d_in[10];
    float* out = (float*)d_out;

    cudaFuncSetAttribute(attn_kernel, cudaFuncAttributeMaxDynamicSharedMemorySize, 70656);

    ln_kernel<<<256, 256>>>(z, ln_g, ln_b);
    projmm_kernel<<<4096, 256>>>(Wq, Wk, Wv, Wg, bg);
    attn_kernel<<<1024, 256, 70656>>>();
    outmm_kernel<<<256, 256>>>(Wo, bo, out);
}

// round 13
// speedup vs baseline: 1.8513x; 1.3204x over previous
#include <cuda_runtime.h>
#include <cuda_bf16.h>
#include <stdint.h>
#include <math.h>

#define SCALE_Q 0.17677669529663687f   // 1/sqrt(32)

// Scratch (static __device__; no allocations allowed)
__device__ __nv_bfloat16 g_znhl[65536*64];     // [r][znh(32)|znl(32)]
__device__ __nv_bfloat16 g_qhl[1024*256*64];   // [ih][j][qh(32)|ql(32)] (pre-scaled)
__device__ __nv_bfloat16 g_khl[1024*256*64];   // [ih][j][kh|kl]
__device__ __nv_bfloat16 g_vhl[1024*256*64];   // [ih][j][vh|vl]
__device__ float g_gate[1024*256*32];
__device__ __nv_bfloat16 g_ohl[65536*256];     // [r][oh(128)|ol(128)], col = h*32+c

__device__ __forceinline__ uint32_t pack_bf2(__nv_bfloat16 a, __nv_bfloat16 b) {
    __nv_bfloat162 t; t.x = a; t.y = b;
    return *reinterpret_cast<uint32_t*>(&t);
}
__device__ __forceinline__ uint32_t split_hi(float a, float b, float* ra, float* rb) {
    __nv_bfloat16 ha = __float2bfloat16(a), hb = __float2bfloat16(b);
    *ra = a - __bfloat162float(ha);
    *rb = b - __bfloat162float(hb);
    return pack_bf2(ha, hb);
}
// Fast pair convert: result low16 = bf16(a), high16 = bf16(b) (1 instr)
__device__ __forceinline__ uint32_t cvt2_bf16(float a, float b) {
    uint32_t r;
    asm("cvt.rn.bf16x2.f32 %0, %1, %2;" : "=r"(r) : "f"(b), "f"(a));
    return r;
}
// Fast split: returns hi pair, residuals via bit reconstruction (6 instr/pair)
__device__ __forceinline__ uint32_t split2(float a, float b, float* la, float* lb) {
    uint32_t h = cvt2_bf16(a, b);
    *la = a - __uint_as_float(h << 16);
    *lb = b - __uint_as_float(h & 0xffff0000u);
    return h;
}

// m16n8k16 row.col bf16 -> f32 accumulate (sm_80+ PTX, valid on compute_103)
__device__ __forceinline__ void mma16816(float* d, const uint32_t* a,
                                         uint32_t b0, uint32_t b1) {
    asm volatile(
        "mma.sync.aligned.m16n8k16.row.col.f32.bf16.bf16.f32 "
        "{%0,%1,%2,%3}, {%4,%5,%6,%7}, {%8,%9}, {%0,%1,%2,%3};"
        : "+f"(d[0]), "+f"(d[1]), "+f"(d[2]), "+f"(d[3])
        : "r"(a[0]), "r"(a[1]), "r"(a[2]), "r"(a[3]), "r"(b0), "r"(b1));
}

// ---------------------------------------------------------------------------
// Kernel 1a: LayerNorm only -> zn bf16 hi/lo rows
// ---------------------------------------------------------------------------
__global__ __launch_bounds__(256) void ln_kernel(
    const float* __restrict__ z, const float* __restrict__ ln_g,
    const float* __restrict__ ln_b)
{
    __shared__ float sg[32], sb[32];
    const int tid = threadIdx.x;
    if (tid < 32) { sg[tid] = ln_g[tid]; sb[tid] = ln_b[tid]; }
    __syncthreads();

    const int r = blockIdx.x * 256 + tid;
    float x[32];
    const float4* zp = (const float4*)(z + (size_t)r * 32);
    #pragma unroll
    for (int c4 = 0; c4 < 8; ++c4) {
        float4 t = zp[c4];
        x[c4*4+0]=t.x; x[c4*4+1]=t.y; x[c4*4+2]=t.z; x[c4*4+3]=t.w;
    }
    float mu = 0.f;
    #pragma unroll
    for (int c = 0; c < 32; ++c) mu += x[c];
    mu *= (1.f/32.f);
    float var = 0.f;
    #pragma unroll
    for (int c = 0; c < 32; ++c) { float d = x[c]-mu; var += d*d; }
    var *= (1.f/32.f);
    const float inv = rsqrtf(var + 1e-5f);

    __nv_bfloat16* row = g_znhl + (size_t)r * 64;
    #pragma unroll
    for (int c = 0; c < 32; c += 2) {
        float a = (x[c]-mu)*inv*sg[c] + sb[c];
        float b = (x[c+1]-mu)*inv*sg[c+1] + sb[c+1];
        float la, lb;
        uint32_t hi = split2(a, b, &la, &lb);
        *(uint32_t*)(row + c)      = hi;
        *(uint32_t*)(row + 32 + c) = cvt2_bf16(la, lb);
    }
}

// ---------------------------------------------------------------------------
// Kernel 1b: projections as split-bf16 HMMA GEMM. (unchanged from R11)
// ---------------------------------------------------------------------------
__global__ __launch_bounds__(256) void projmm_kernel(
    const float* __restrict__ Wq, const float* __restrict__ Wk,
    const float* __restrict__ Wv, const float* __restrict__ Wg,
    const float* __restrict__ bg)
{
    __shared__ uint32_t sW[128*36];
    __shared__ uint32_t sA[64*36];
    __shared__ float sbg[128];

    const int tid = threadIdx.x;
    const int mat = blockIdx.x & 3;
    const int r0  = (blockIdx.x >> 2) * 64;
    const float* W = (mat == 0) ? Wq : (mat == 1) ? Wk : (mat == 2) ? Wv : Wg;

    {
        const int row = tid >> 1, half = tid & 1;
        const float4* wp = (const float4*)(W + row*32 + half*16);
        #pragma unroll
        for (int q4 = 0; q4 < 4; ++q4) {
            float4 wv = wp[q4];
            float lx, ly, lz, lw;
            uint32_t h0 = split2(wv.x, wv.y, &lx, &ly);
            uint32_t h1 = split2(wv.z, wv.w, &lz, &lw);
            const int w0 = half*8 + q4*2;
            sW[row*36 + w0]      = h0;
            sW[row*36 + w0 + 1]  = h1;
            sW[row*36 + 16 + w0]     = cvt2_bf16(lx, ly);
            sW[row*36 + 16 + w0 + 1] = cvt2_bf16(lz, lw);
        }
    }
    if (tid < 128) sbg[tid] = bg[tid];
    {
        const uint2* ag = (const uint2*)(g_znhl + (size_t)r0 * 64);
        uint2* sA2 = (uint2*)sA;
        for (int x = tid; x < 1024; x += 256) {
            int row = x >> 4, w = x & 15;
            sA2[row*18 + w] = ag[row*16 + w];
        }
    }
    __syncthreads();

    const int warp = tid >> 5, lane = tid & 31;
    const int l4 = lane & 3, ld4 = lane >> 2;
    const int mrow = (warp & 1) * 32;
    const int ncol = (warp >> 1) * 32;

    uint32_t Ah[2][2][4], Al[2][2][4];
    #pragma unroll
    for (int mt = 0; mt < 2; ++mt)
    #pragma unroll
    for (int kt = 0; kt < 2; ++kt) {
        const int r = mrow + mt*16 + ld4;
        const uint32_t* p0 = sA + r*36 + kt*8 + l4;
        const uint32_t* p1 = sA + (r+8)*36 + kt*8 + l4;
        Ah[mt][kt][0] = p0[0];  Ah[mt][kt][1] = p1[0];
        Ah[mt][kt][2] = p0[4];  Ah[mt][kt][3] = p1[4];
        Al[mt][kt][0] = p0[16]; Al[mt][kt][1] = p1[16];
        Al[mt][kt][2] = p0[20]; Al[mt][kt][3] = p1[20];
    }

    const int ig = r0 >> 8;
    #pragma unroll
    for (int nt = 0; nt < 4; ++nt) {
        const int n = ncol + nt*8 + ld4;
        const uint32_t* wp = sW + n*36 + l4;
        uint32_t bh[2][2], bl[2][2];
        bh[0][0]=wp[0];  bh[0][1]=wp[4];  bh[1][0]=wp[8];  bh[1][1]=wp[12];
        bl[0][0]=wp[16]; bl[0][1]=wp[20]; bl[1][0]=wp[24]; bl[1][1]=wp[28];
        #pragma unroll
        for (int mt = 0; mt < 2; ++mt) {
            float s[4] = {0,0,0,0}, s2[4] = {0,0,0,0};
            mma16816(s,  Ah[mt][0], bh[0][0], bh[0][1]);
            mma16816(s,  Ah[mt][1], bh[1][0], bh[1][1]);
            mma16816(s2, Ah[mt][0], bl[0][0], bl[0][1]);
            mma16816(s2, Ah[mt][1], bl[1][0], bl[1][1]);
            mma16816(s2, Al[mt][0], bh[0][0], bh[0][1]);
            mma16816(s2, Al[mt][1], bh[1][0], bh[1][1]);
            #pragma unroll
            for (int u = 0; u < 4; ++u) s[u] += s2[u];

            const int rg0 = r0 + mrow + mt*16 + ld4;
            const int ocol = ncol + nt*8 + l4*2;
            const int h = ocol >> 5, c = ocol & 31;
            const int j0 = rg0 & 255;
            const size_t base = ((size_t)(ig*4 + h)*256);
            if (mat == 3) {
                float* g0 = g_gate + (base + j0)*32;
                float* g1 = g_gate + (base + j0 + 8)*32;
                *(float2*)(g0 + c) = make_float2(
                    1.f/(1.f+__expf(-(s[0]+sbg[ocol]))), 1.f/(1.f+__expf(-(s[1]+sbg[ocol+1]))));
                *(float2*)(g1 + c) = make_float2(
                    1.f/(1.f+__expf(-(s[2]+sbg[ocol]))), 1.f/(1.f+__expf(-(s[3]+sbg[ocol+1]))));
            } else {
                if (mat == 0) {
                    #pragma unroll
                    for (int u = 0; u < 4; ++u) s[u] *= SCALE_Q;
                }
                __nv_bfloat16* dst = (mat == 0) ? g_qhl : (mat == 1) ? g_khl : g_vhl;
                __nv_bfloat16* d0 = dst + (base + j0)*64;
                __nv_bfloat16* d1 = dst + (base + j0 + 8)*64;
                float la, lb;
                uint32_t hi0 = split2(s[0], s[1], &la, &lb);
                *(uint32_t*)(d0 + c)      = hi0;
                *(uint32_t*)(d0 + 32 + c) = cvt2_bf16(la, lb);
                uint32_t hi1 = split2(s[2], s[3], &la, &lb);
                *(uint32_t*)(d1 + c)      = hi1;
                *(uint32_t*)(d1 + 32 + c) = cvt2_bf16(la, lb);
            }
        }
    }
}

// ---------------------------------------------------------------------------
// Kernel 2: HMMA attention. One CTA per (i,h); 8 warps x 32 query rows.
// 2 CTAs/SM (launch_bounds cap 128 regs); per-kt-half processing halves
// P-fragment live range; fast bf16x2 splits.
// ---------------------------------------------------------------------------
__global__ __launch_bounds__(256, 2) void attn_kernel()
{
    extern __shared__ __align__(16) char smem[];
    uint32_t* sK = (uint32_t*)smem;                       // 36864 B
    __nv_bfloat16* sVh = (__nv_bfloat16*)(sK + 256*36);   // 16896 B
    __nv_bfloat16* sVl = sVh + 32*264;                    // 16896 B

    const int tid = threadIdx.x;
    const int ih = blockIdx.x;
    const int warp = tid >> 5, lane = tid & 31;
    const int l4 = lane & 3, ld4 = lane >> 2;
    const int m0 = warp * 32;

    uint32_t Qh[2][2][4], Ql[2][2][4];
    {
        const uint32_t* qgw = (const uint32_t*)(g_qhl + (size_t)ih*16384);
        #pragma unroll
        for (int mt = 0; mt < 2; ++mt)
        #pragma unroll
        for (int kt = 0; kt < 2; ++kt) {
            const int r = m0 + mt*16 + ld4;
            const uint32_t* p0 = qgw + r*32 + kt*8 + l4;
            const uint32_t* p1 = qgw + (r+8)*32 + kt*8 + l4;
            Qh[mt][kt][0] = p0[0];  Qh[mt][kt][1] = p1[0];
            Qh[mt][kt][2] = p0[4];  Qh[mt][kt][3] = p1[4];
            Ql[mt][kt][0] = p0[16]; Ql[mt][kt][1] = p1[16];
            Ql[mt][kt][2] = p0[20]; Ql[mt][kt][3] = p1[20];
        }
    }
    {
        const uint2* kg = (const uint2*)(g_khl + (size_t)ih*16384);
        uint2* sK2 = (uint2*)sK;
        for (int x = tid; x < 4096; x += 256) {
            int row = x >> 4, w = x & 15;
            sK2[row*18 + w] = kg[x];
        }
    }
    {
        const uint4* vg = (const uint4*)(g_vhl + (size_t)ih*16384) + tid*8;
        uint32_t vb[32];
        #pragma unroll
        for (int t = 0; t < 8; ++t) {
            uint4 u = vg[t];
            vb[t*4+0]=u.x; vb[t*4+1]=u.y; vb[t*4+2]=u.z; vb[t*4+3]=u.w;
        }
        const __nv_bfloat16* vbh = (const __nv_bfloat16*)vb;
        #pragma unroll
        for (int c = 0; c < 32; ++c) {
            sVh[c*264 + tid] = vbh[c];
            sVl[c*264 + tid] = vbh[32 + c];
        }
    }
    __syncthreads();

    float acc[2][4][4];
    #pragma unroll
    for (int mt = 0; mt < 2; ++mt)
    #pragma unroll
    for (int nt = 0; nt < 4; ++nt)
    #pragma unroll
    for (int u = 0; u < 4; ++u) acc[mt][nt][u] = 0.f;
    float dsum[2][2] = {{0.f,0.f},{0.f,0.f}};

    const uint32_t* sVhw = (const uint32_t*)sVh;
    const uint32_t* sVlw = (const uint32_t*)sVl;

    for (int ch = 0; ch < 8; ++ch) {
        #pragma unroll
        for (int kt = 0; kt < 2; ++kt) {       // 16-wide KV half
            uint32_t Ph[2][4], Pl[2][4];       // P frags for this half only
            #pragma unroll
            for (int nt2 = 0; nt2 < 2; ++nt2) {
                const int nt = kt*2 + nt2;
                const int n = ch*32 + nt*8 + ld4;
                const uint32_t* kp = sK + n*36 + l4;
                uint32_t bh[2][2], bl[2][2];
                bh[0][0]=kp[0];  bh[0][1]=kp[4];  bh[1][0]=kp[8];  bh[1][1]=kp[12];
                bl[0][0]=kp[16]; bl[0][1]=kp[20]; bl[1][0]=kp[24]; bl[1][1]=kp[28];
                #pragma unroll
                for (int mt = 0; mt < 2; ++mt) {
                    float s[4] = {0,0,0,0}, s2[4] = {0,0,0,0};
                    mma16816(s,  Qh[mt][0], bh[0][0], bh[0][1]);
                    mma16816(s,  Qh[mt][1], bh[1][0], bh[1][1]);
                    mma16816(s2, Qh[mt][0], bl[0][0], bl[0][1]);
                    mma16816(s2, Qh[mt][1], bl[1][0], bl[1][1]);
                    mma16816(s2, Ql[mt][0], bh[0][0], bh[0][1]);
                    mma16816(s2, Ql[mt][1], bh[1][0], bh[1][1]);
                    const float e0 = __expf(s[0]+s2[0]), e1 = __expf(s[1]+s2[1]);
                    const float e2 = __expf(s[2]+s2[2]), e3 = __expf(s[3]+s2[3]);
                    dsum[mt][0] += e0 + e1;
                    dsum[mt][1] += e2 + e3;
                    float l0, l1, l2, l3;
                    Ph[mt][nt2*2+0] = split2(e0, e1, &l0, &l1);
                    Ph[mt][nt2*2+1] = split2(e2, e3, &l2, &l3);
                    Pl[mt][nt2*2+0] = cvt2_bf16(l0, l1);
                    Pl[mt][nt2*2+1] = cvt2_bf16(l2, l3);
                }
            }
            // AV for this 16-wide half
            #pragma unroll
            for (int ntc = 0; ntc < 4; ++ntc) {
                const int c = ntc*8 + ld4;
                const uint32_t* vhp = sVhw + c*132 + ch*16 + kt*8 + l4;
                const uint32_t* vlp = sVlw + c*132 + ch*16 + kt*8 + l4;
                const uint32_t vh0 = vhp[0], vh1 = vhp[4];
                const uint32_t vl0 = vlp[0], vl1 = vlp[4];
                #pragma unroll
                for (int mt = 0; mt < 2; ++mt) {
                    mma16816(acc[mt][ntc], Ph[mt], vh0, vh1);
                    mma16816(acc[mt][ntc], Ph[mt], vl0, vl1);
                    mma16816(acc[mt][ntc], Pl[mt], vh0, vh1);
                }
            }
        }
    }

    #pragma unroll
    for (int mt = 0; mt < 2; ++mt)
    #pragma unroll
    for (int rr = 0; rr < 2; ++rr) {
        float d = dsum[mt][rr];
        d += __shfl_xor_sync(0xffffffffu, d, 1);
        d += __shfl_xor_sync(0xffffffffu, d, 2);
        dsum[mt][rr] = 1.f / d;
    }

    // Epilogue: normalize, gate, split bf16 hi/lo -> g_ohl [r][128 | 128]
    const int rbase = (ih >> 2) * 256;
    const int cbase = (ih & 3) * 32;
    const size_t gbase = (size_t)ih * 8192;
    uint32_t* ow = (uint32_t*)g_ohl;
    #pragma unroll
    for (int mt = 0; mt < 2; ++mt) {
        const int q0 = m0 + mt*16 + ld4;
        #pragma unroll
        for (int ntc = 0; ntc < 4; ++ntc) {
            const int c0 = ntc*8 + l4*2;
            const int wcol = (cbase + c0) >> 1;
            {
                float2 gv = *(const float2*)(g_gate + gbase + q0*32 + c0);
                float o0 = acc[mt][ntc][0] * dsum[mt][0] * gv.x;
                float o1 = acc[mt][ntc][1] * dsum[mt][0] * gv.y;
                float l0, l1;
                uint32_t hi = split2(o0, o1, &l0, &l1);
                uint32_t* base = ow + (size_t)(rbase + q0) * 128 + wcol;
                base[0]  = hi;
                base[64] = cvt2_bf16(l0, l1);
            }
            {
                float2 gv = *(const float2*)(g_gate + gbase + (q0+8)*32 + c0);
                float o0 = acc[mt][ntc][2] * dsum[mt][1] * gv.x;
                float o1 = acc[mt][ntc][3] * dsum[mt][1] * gv.y;
                float l0, l1;
                uint32_t hi = split2(o0, o1, &l0, &l1);
                uint32_t* base = ow + (size_t)(rbase + q0 + 8) * 128 + wcol;
                base[0]  = hi;
                base[64] = cvt2_bf16(l0, l1);
            }
        }
    }
}

// ---------------------------------------------------------------------------
// Kernel 3: out = o @ Wo.T + bo as split-bf16 HMMA GEMM. (unchanged from R12)
// ---------------------------------------------------------------------------
__global__ __launch_bounds__(256) void outmm_kernel(
    const float* __restrict__ Wo, const float* __restrict__ bo,
    float* __restrict__ out)
{
    __shared__ uint32_t sW[32*132];
    __shared__ float sbo[32];
    const int tid = threadIdx.x;
    {
        const int row = tid >> 3, seg = tid & 7;
        const float4* wp = (const float4*)(Wo + row*128 + seg*16);
        #pragma unroll
        for (int q4 = 0; q4 < 4; ++q4) {
            float4 w = wp[q4];
            float lx, ly, lz, lw;
            uint32_t h0 = split2(w.x, w.y, &lx, &ly);
            uint32_t h1 = split2(w.z, w.w, &lz, &lw);
            const int w0 = seg*8 + q4*2;
            sW[row*132 + w0]          = h0;
            sW[row*132 + w0 + 1]      = h1;
            sW[row*132 + 64 + w0]     = cvt2_bf16(lx, ly);
            sW[row*132 + 64 + w0 + 1] = cvt2_bf16(lz, lw);
        }
    }
    if (tid < 32) sbo[tid] = bo[tid];
    __syncthreads();

    const int warp = tid >> 5, lane = tid & 31;
    const int l4 = lane & 3, ld4 = lane >> 2;
    const int m0 = blockIdx.x * 256 + warp * 32;

    float acc[2][4][4];
    #pragma unroll
    for (int mt = 0; mt < 2; ++mt)
    #pragma unroll
    for (int nt = 0; nt < 4; ++nt)
    #pragma unroll
    for (int u = 0; u < 4; ++u) acc[mt][nt][u] = 0.f;

    const uint32_t* A = (const uint32_t*)g_ohl;

    #pragma unroll
    for (int kc = 0; kc < 4; ++kc) {
        uint32_t Ah[2][2][4], Al[2][2][4];
        #pragma unroll
        for (int mt = 0; mt < 2; ++mt)
        #pragma unroll
        for (int kt = 0; kt < 2; ++kt) {
            const uint32_t* p0 = A + (size_t)(m0 + mt*16 + ld4) * 128 + kc*16 + kt*8 + l4;
            const uint32_t* p1 = p0 + 8*128;
            Ah[mt][kt][0] = p0[0];  Ah[mt][kt][1] = p1[0];
            Ah[mt][kt][2] = p0[4];  Ah[mt][kt][3] = p1[4];
            Al[mt][kt][0] = p0[64]; Al[mt][kt][1] = p1[64];
            Al[mt][kt][2] = p0[68]; Al[mt][kt][3] = p1[68];
        }
        #pragma unroll
        for (int nt = 0; nt < 4; ++nt) {
            const uint32_t* wp = sW + (nt*8 + ld4)*132 + kc*16 + l4;
            uint32_t bh[2][2], bl[2][2];
            bh[0][0]=wp[0];  bh[0][1]=wp[4];  bh[1][0]=wp[8];  bh[1][1]=wp[12];
            bl[0][0]=wp[64]; bl[0][1]=wp[68]; bl[1][0]=wp[72]; bl[1][1]=wp[76];
            #pragma unroll
            for (int mt = 0; mt < 2; ++mt) {
                #pragma unroll
                for (int kt = 0; kt < 2; ++kt) {
                    mma16816(acc[mt][nt], Ah[mt][kt], bh[kt][0], bh[kt][1]);
                    mma16816(acc[mt][nt], Ah[mt][kt], bl[kt][0], bl[kt][1]);
                    mma16816(acc[mt][nt], Al[mt][kt], bh[kt][0], bh[kt][1]);
                }
            }
        }
    }

    #pragma unroll
    for (int mt = 0; mt < 2; ++mt) {
        const int r0 = m0 + mt*16 + ld4;
        #pragma unroll
        for (int nt = 0; nt < 4; ++nt) {
            const int c0 = nt*8 + l4*2;
            *(float2*)(out + (size_t)r0*32 + c0) =
                make_float2(acc[mt][nt][0] + sbo[c0], acc[mt][nt][1] + sbo[c0+1]);
            *(float2*)(out + (size_t)(r0+8)*32 + c0) =
                make_float2(acc[mt][nt][2] + sbo[c0], acc[mt][nt][3] + sbo[c0+1]);
        }
    }
}

// ---------------------------------------------------------------------------
extern "C" void kernel_launch(void* const* d_in, const int* in_sizes, int n_in,
                              void* d_out, int out_size) {
    const float* z    = (const float*)d_in[0];
    const float* ln_g = (const float*)d_in[1];
    const float* ln_b = (const float*)d_in[2];
    const float* Wq   = (const float*)d_in[3];
    const float* Wk   = (const float*)d_in[4];
    const float* Wv   = (const float*)d_in[5];
    // d_in[6] = Wb: bias is constant along the softmax axis -> cancels exactly
    const float* Wg   = (const float*)d_in[7];
    const float* bg   = (const float*)d_in[8];
    const float* Wo   = (const float*)d_in[9];
    const float* bo   = (const float*)d_in[10];
    float* out = (float*)d_out;

    cudaFuncSetAttribute(attn_kernel, cudaFuncAttributeMaxDynamicSharedMemorySize, 70656);

    ln_kernel<<<256, 256>>>(z, ln_g, ln_b);
    projmm_kernel<<<4096, 256>>>(Wq, Wk, Wv, Wg, bg);
    attn_kernel<<<1024, 256, 70656>>>();
    outmm_kernel<<<256, 256>>>(Wo, bo, out);
}

// round 14
// speedup vs baseline: 1.9505x; 1.0536x over previous
#include <cuda_runtime.h>
#include <cuda_bf16.h>
#include <stdint.h>
#include <math.h>

// q pre-scale: 1/sqrt(32) * log2(e)  (so attn can use exp2f directly)
#define SCALE_Q_EXP2 (0.17677669529663687f * 1.4426950408889634f)

// Scratch (static __device__; no allocations allowed)
__device__ __nv_bfloat16 g_znhl[65536*64];     // [r][znh(32)|znl(32)]
__device__ __nv_bfloat16 g_qhl[1024*256*64];   // [ih][j][qh(32)|ql(32)] (pre-scaled)
__device__ __nv_bfloat16 g_khl[1024*256*64];   // [ih][j][kh|kl]
__device__ __nv_bfloat16 g_vhl[1024*256*64];   // [ih][j][vh|vl]
__device__ float g_gate[1024*256*32];
__device__ __nv_bfloat16 g_ohl[65536*256];     // [r][oh(128)|ol(128)], col = h*32+c

// Fast pair convert: result low16 = bf16(a), high16 = bf16(b) (1 instr)
__device__ __forceinline__ uint32_t cvt2_bf16(float a, float b) {
    uint32_t r;
    asm("cvt.rn.bf16x2.f32 %0, %1, %2;" : "=r"(r) : "f"(b), "f"(a));
    return r;
}
// Fast split: returns hi pair, residuals via bit reconstruction
__device__ __forceinline__ uint32_t split2(float a, float b, float* la, float* lb) {
    uint32_t h = cvt2_bf16(a, b);
    *la = a - __uint_as_float(h << 16);
    *lb = b - __uint_as_float(h & 0xffff0000u);
    return h;
}

// m16n8k16 row.col bf16 -> f32 accumulate (sm_80+ PTX, valid on compute_103)
__device__ __forceinline__ void mma16816(float* d, const uint32_t* a,
                                         uint32_t b0, uint32_t b1) {
    asm volatile(
        "mma.sync.aligned.m16n8k16.row.col.f32.bf16.bf16.f32 "
        "{%0,%1,%2,%3}, {%4,%5,%6,%7}, {%8,%9}, {%0,%1,%2,%3};"
        : "+f"(d[0]), "+f"(d[1]), "+f"(d[2]), "+f"(d[3])
        : "r"(a[0]), "r"(a[1]), "r"(a[2]), "r"(a[3]), "r"(b0), "r"(b1));
}

// ---------------------------------------------------------------------------
// Kernel 1a: LayerNorm only -> zn bf16 hi/lo rows
// ---------------------------------------------------------------------------
__global__ __launch_bounds__(256) void ln_kernel(
    const float* __restrict__ z, const float* __restrict__ ln_g,
    const float* __restrict__ ln_b)
{
    __shared__ float sg[32], sb[32];
    const int tid = threadIdx.x;
    if (tid < 32) { sg[tid] = ln_g[tid]; sb[tid] = ln_b[tid]; }
    __syncthreads();

    const int r = blockIdx.x * 256 + tid;
    float x[32];
    const float4* zp = (const float4*)(z + (size_t)r * 32);
    #pragma unroll
    for (int c4 = 0; c4 < 8; ++c4) {
        float4 t = zp[c4];
        x[c4*4+0]=t.x; x[c4*4+1]=t.y; x[c4*4+2]=t.z; x[c4*4+3]=t.w;
    }
    float mu = 0.f;
    #pragma unroll
    for (int c = 0; c < 32; ++c) mu += x[c];
    mu *= (1.f/32.f);
    float var = 0.f;
    #pragma unroll
    for (int c = 0; c < 32; ++c) { float d = x[c]-mu; var += d*d; }
    var *= (1.f/32.f);
    const float inv = rsqrtf(var + 1e-5f);

    __nv_bfloat16* row = g_znhl + (size_t)r * 64;
    #pragma unroll
    for (int c = 0; c < 32; c += 2) {
        float a = (x[c]-mu)*inv*sg[c] + sb[c];
        float b = (x[c+1]-mu)*inv*sg[c+1] + sb[c+1];
        float la, lb;
        uint32_t hi = split2(a, b, &la, &lb);
        *(uint32_t*)(row + c)      = hi;
        *(uint32_t*)(row + 32 + c) = cvt2_bf16(la, lb);
    }
}

// ---------------------------------------------------------------------------
// Kernel 1b: projections as split-bf16 HMMA GEMM.
// q is pre-scaled by SCALE_Q_EXP2 (1/sqrt(C) * log2 e) for the exp2 softmax.
// ---------------------------------------------------------------------------
__global__ __launch_bounds__(256) void projmm_kernel(
    const float* __restrict__ Wq, const float* __restrict__ Wk,
    const float* __restrict__ Wv, const float* __restrict__ Wg,
    const float* __restrict__ bg)
{
    __shared__ uint32_t sW[128*36];
    __shared__ uint32_t sA[64*36];
    __shared__ float sbg[128];

    const int tid = threadIdx.x;
    const int mat = blockIdx.x & 3;
    const int r0  = (blockIdx.x >> 2) * 64;
    const float* W = (mat == 0) ? Wq : (mat == 1) ? Wk : (mat == 2) ? Wv : Wg;

    {
        const int row = tid >> 1, half = tid & 1;
        const float4* wp = (const float4*)(W + row*32 + half*16);
        #pragma unroll
        for (int q4 = 0; q4 < 4; ++q4) {
            float4 wv = wp[q4];
            float lx, ly, lz, lw;
            uint32_t h0 = split2(wv.x, wv.y, &lx, &ly);
            uint32_t h1 = split2(wv.z, wv.w, &lz, &lw);
            const int w0 = half*8 + q4*2;
            sW[row*36 + w0]      = h0;
            sW[row*36 + w0 + 1]  = h1;
            sW[row*36 + 16 + w0]     = cvt2_bf16(lx, ly);
            sW[row*36 + 16 + w0 + 1] = cvt2_bf16(lz, lw);
        }
    }
    if (tid < 128) sbg[tid] = bg[tid];
    {
        const uint2* ag = (const uint2*)(g_znhl + (size_t)r0 * 64);
        uint2* sA2 = (uint2*)sA;
        for (int x = tid; x < 1024; x += 256) {
            int row = x >> 4, w = x & 15;
            sA2[row*18 + w] = ag[row*16 + w];
        }
    }
    __syncthreads();

    const int warp = tid >> 5, lane = tid & 31;
    const int l4 = lane & 3, ld4 = lane >> 2;
    const int mrow = (warp & 1) * 32;
    const int ncol = (warp >> 1) * 32;

    uint32_t Ah[2][2][4], Al[2][2][4];
    #pragma unroll
    for (int mt = 0; mt < 2; ++mt)
    #pragma unroll
    for (int kt = 0; kt < 2; ++kt) {
        const int r = mrow + mt*16 + ld4;
        const uint32_t* p0 = sA + r*36 + kt*8 + l4;
        const uint32_t* p1 = sA + (r+8)*36 + kt*8 + l4;
        Ah[mt][kt][0] = p0[0];  Ah[mt][kt][1] = p1[0];
        Ah[mt][kt][2] = p0[4];  Ah[mt][kt][3] = p1[4];
        Al[mt][kt][0] = p0[16]; Al[mt][kt][1] = p1[16];
        Al[mt][kt][2] = p0[20]; Al[mt][kt][3] = p1[20];
    }

    const int ig = r0 >> 8;
    #pragma unroll
    for (int nt = 0; nt < 4; ++nt) {
        const int n = ncol + nt*8 + ld4;
        const uint32_t* wp = sW + n*36 + l4;
        uint32_t bh[2][2], bl[2][2];
        bh[0][0]=wp[0];  bh[0][1]=wp[4];  bh[1][0]=wp[8];  bh[1][1]=wp[12];
        bl[0][0]=wp[16]; bl[0][1]=wp[20]; bl[1][0]=wp[24]; bl[1][1]=wp[28];
        #pragma unroll
        for (int mt = 0; mt < 2; ++mt) {
            float s[4] = {0,0,0,0}, s2[4] = {0,0,0,0};
            mma16816(s,  Ah[mt][0], bh[0][0], bh[0][1]);
            mma16816(s,  Ah[mt][1], bh[1][0], bh[1][1]);
            mma16816(s2, Ah[mt][0], bl[0][0], bl[0][1]);
            mma16816(s2, Ah[mt][1], bl[1][0], bl[1][1]);
            mma16816(s2, Al[mt][0], bh[0][0], bh[0][1]);
            mma16816(s2, Al[mt][1], bh[1][0], bh[1][1]);
            #pragma unroll
            for (int u = 0; u < 4; ++u) s[u] += s2[u];

            const int rg0 = r0 + mrow + mt*16 + ld4;
            const int ocol = ncol + nt*8 + l4*2;
            const int h = ocol >> 5, c = ocol & 31;
            const int j0 = rg0 & 255;
            const size_t base = ((size_t)(ig*4 + h)*256);
            if (mat == 3) {
                float* g0 = g_gate + (base + j0)*32;
                float* g1 = g_gate + (base + j0 + 8)*32;
                *(float2*)(g0 + c) = make_float2(
                    1.f/(1.f+__expf(-(s[0]+sbg[ocol]))), 1.f/(1.f+__expf(-(s[1]+sbg[ocol+1]))));
                *(float2*)(g1 + c) = make_float2(
                    1.f/(1.f+__expf(-(s[2]+sbg[ocol]))), 1.f/(1.f+__expf(-(s[3]+sbg[ocol+1]))));
            } else {
                if (mat == 0) {
                    #pragma unroll
                    for (int u = 0; u < 4; ++u) s[u] *= SCALE_Q_EXP2;
                }
                __nv_bfloat16* dst = (mat == 0) ? g_qhl : (mat == 1) ? g_khl : g_vhl;
                __nv_bfloat16* d0 = dst + (base + j0)*64;
                __nv_bfloat16* d1 = dst + (base + j0 + 8)*64;
                float la, lb;
                uint32_t hi0 = split2(s[0], s[1], &la, &lb);
                *(uint32_t*)(d0 + c)      = hi0;
                *(uint32_t*)(d0 + 32 + c) = cvt2_bf16(la, lb);
                uint32_t hi1 = split2(s[2], s[3], &la, &lb);
                *(uint32_t*)(d1 + c)      = hi1;
                *(uint32_t*)(d1 + 32 + c) = cvt2_bf16(la, lb);
            }
        }
    }
}

// ---------------------------------------------------------------------------
// Kernel 2: HMMA attention. One CTA per (i,h); 8 warps; TWO sequential
// mt-passes of 16 query rows each -> regs fit 3 CTAs/SM (24 warps/SM).
// Softmax via exp2f (q pre-scaled by log2 e).
// ---------------------------------------------------------------------------
__global__ __launch_bounds__(256, 3) void attn_kernel()
{
    extern __shared__ __align__(16) char smem[];
    uint32_t* sK = (uint32_t*)smem;                       // 36864 B
    __nv_bfloat16* sVh = (__nv_bfloat16*)(sK + 256*36);   // 16896 B
    __nv_bfloat16* sVl = sVh + 32*264;                    // 16896 B

    const int tid = threadIdx.x;
    const int ih = blockIdx.x;
    const int warp = tid >> 5, lane = tid & 31;
    const int l4 = lane & 3, ld4 = lane >> 2;
    const int m0 = warp * 32;

    // Stage K rows (full row = 16 uint2)
    {
        const uint2* kg = (const uint2*)(g_khl + (size_t)ih*16384);
        uint2* sK2 = (uint2*)sK;
        for (int x = tid; x < 4096; x += 256) {
            int row = x >> 4, w = x & 15;
            sK2[row*18 + w] = kg[x];
        }
    }
    // Stage V transposed: thread j handles row j
    {
        const uint4* vg = (const uint4*)(g_vhl + (size_t)ih*16384) + tid*8;
        uint32_t vb[32];
        #pragma unroll
        for (int t = 0; t < 8; ++t) {
            uint4 u = vg[t];
            vb[t*4+0]=u.x; vb[t*4+1]=u.y; vb[t*4+2]=u.z; vb[t*4+3]=u.w;
        }
        const __nv_bfloat16* vbh = (const __nv_bfloat16*)vb;
        #pragma unroll
        for (int c = 0; c < 32; ++c) {
            sVh[c*264 + tid] = vbh[c];
            sVl[c*264 + tid] = vbh[32 + c];
        }
    }
    __syncthreads();

    const uint32_t* sVhw = (const uint32_t*)sVh;
    const uint32_t* sVlw = (const uint32_t*)sVl;
    const uint32_t* qgw = (const uint32_t*)(g_qhl + (size_t)ih*16384);
    const int rbase = (ih >> 2) * 256;
    const int cbase = (ih & 3) * 32;
    const size_t gbase = (size_t)ih * 8192;
    uint32_t* ow = (uint32_t*)g_ohl;

    #pragma unroll 1
    for (int mt = 0; mt < 2; ++mt) {
        // Q fragments for this 16-row pass only
        uint32_t Qh[2][4], Ql[2][4];
        #pragma unroll
        for (int kt = 0; kt < 2; ++kt) {
            const int r = m0 + mt*16 + ld4;
            const uint32_t* p0 = qgw + r*32 + kt*8 + l4;
            const uint32_t* p1 = qgw + (r+8)*32 + kt*8 + l4;
            Qh[kt][0] = p0[0];  Qh[kt][1] = p1[0];
            Qh[kt][2] = p0[4];  Qh[kt][3] = p1[4];
            Ql[kt][0] = p0[16]; Ql[kt][1] = p1[16];
            Ql[kt][2] = p0[20]; Ql[kt][3] = p1[20];
        }

        float acc[4][4];
        #pragma unroll
        for (int nt = 0; nt < 4; ++nt)
        #pragma unroll
        for (int u = 0; u < 4; ++u) acc[nt][u] = 0.f;
        float dsum0 = 0.f, dsum1 = 0.f;

        for (int ch = 0; ch < 8; ++ch) {
            #pragma unroll
            for (int kt = 0; kt < 2; ++kt) {       // 16-wide KV half
                uint32_t Ph[4], Pl[4];
                #pragma unroll
                for (int nt2 = 0; nt2 < 2; ++nt2) {
                    const int nt = kt*2 + nt2;
                    const int n = ch*32 + nt*8 + ld4;
                    const uint32_t* kp = sK + n*36 + l4;
                    uint32_t bh[2][2], bl[2][2];
                    bh[0][0]=kp[0];  bh[0][1]=kp[4];  bh[1][0]=kp[8];  bh[1][1]=kp[12];
                    bl[0][0]=kp[16]; bl[0][1]=kp[20]; bl[1][0]=kp[24]; bl[1][1]=kp[28];
                    float s[4] = {0,0,0,0}, s2[4] = {0,0,0,0};
                    mma16816(s,  Qh[0], bh[0][0], bh[0][1]);
                    mma16816(s,  Qh[1], bh[1][0], bh[1][1]);
                    mma16816(s2, Qh[0], bl[0][0], bl[0][1]);
                    mma16816(s2, Qh[1], bl[1][0], bl[1][1]);
                    mma16816(s2, Ql[0], bh[0][0], bh[0][1]);
                    mma16816(s2, Ql[1], bh[1][0], bh[1][1]);
                    const float e0 = exp2f(s[0]+s2[0]), e1 = exp2f(s[1]+s2[1]);
                    const float e2 = exp2f(s[2]+s2[2]), e3 = exp2f(s[3]+s2[3]);
                    dsum0 += e0 + e1;
                    dsum1 += e2 + e3;
                    float l0, l1, l2, l3;
                    Ph[nt2*2+0] = split2(e0, e1, &l0, &l1);
                    Ph[nt2*2+1] = split2(e2, e3, &l2, &l3);
                    Pl[nt2*2+0] = cvt2_bf16(l0, l1);
                    Pl[nt2*2+1] = cvt2_bf16(l2, l3);
                }
                // AV for this 16-wide half
                #pragma unroll
                for (int ntc = 0; ntc < 4; ++ntc) {
                    const int c = ntc*8 + ld4;
                    const uint32_t* vhp = sVhw + c*132 + ch*16 + kt*8 + l4;
                    const uint32_t* vlp = sVlw + c*132 + ch*16 + kt*8 + l4;
                    const uint32_t vh0 = vhp[0], vh1 = vhp[4];
                    const uint32_t vl0 = vlp[0], vl1 = vlp[4];
                    mma16816(acc[ntc], Ph, vh0, vh1);
                    mma16816(acc[ntc], Ph, vl0, vl1);
                    mma16816(acc[ntc], Pl, vh0, vh1);
                }
            }
        }

        // Row-sum reduce across the quad, invert
        dsum0 += __shfl_xor_sync(0xffffffffu, dsum0, 1);
        dsum0 += __shfl_xor_sync(0xffffffffu, dsum0, 2);
        dsum1 += __shfl_xor_sync(0xffffffffu, dsum1, 1);
        dsum1 += __shfl_xor_sync(0xffffffffu, dsum1, 2);
        dsum0 = 1.f / dsum0;
        dsum1 = 1.f / dsum1;

        // Epilogue for this pass: normalize, gate, split bf16 hi/lo -> g_ohl
        const int q0 = m0 + mt*16 + ld4;
        #pragma unroll
        for (int ntc = 0; ntc < 4; ++ntc) {
            const int c0 = ntc*8 + l4*2;
            const int wcol = (cbase + c0) >> 1;
            {
                float2 gv = *(const float2*)(g_gate + gbase + q0*32 + c0);
                float o0 = acc[ntc][0] * dsum0 * gv.x;
                float o1 = acc[ntc][1] * dsum0 * gv.y;
                float l0, l1;
                uint32_t hi = split2(o0, o1, &l0, &l1);
                uint32_t* base = ow + (size_t)(rbase + q0) * 128 + wcol;
                base[0]  = hi;
                base[64] = cvt2_bf16(l0, l1);
            }
            {
                float2 gv = *(const float2*)(g_gate + gbase + (q0+8)*32 + c0);
                float o0 = acc[ntc][2] * dsum1 * gv.x;
                float o1 = acc[ntc][3] * dsum1 * gv.y;
                float l0, l1;
                uint32_t hi = split2(o0, o1, &l0, &l1);
                uint32_t* base = ow + (size_t)(rbase + q0 + 8) * 128 + wcol;
                base[0]  = hi;
                base[64] = cvt2_bf16(l0, l1);
            }
        }
    }
}

// ---------------------------------------------------------------------------
// Kernel 3: out = o @ Wo.T + bo as split-bf16 HMMA GEMM. (unchanged)
// ---------------------------------------------------------------------------
__global__ __launch_bounds__(256) void outmm_kernel(
    const float* __restrict__ Wo, const float* __restrict__ bo,
    float* __restrict__ out)
{
    __shared__ uint32_t sW[32*132];
    __shared__ float sbo[32];
    const int tid = threadIdx.x;
    {
        const int row = tid >> 3, seg = tid & 7;
        const float4* wp = (const float4*)(Wo + row*128 + seg*16);
        #pragma unroll
        for (int q4 = 0; q4 < 4; ++q4) {
            float4 w = wp[q4];
            float lx, ly, lz, lw;
            uint32_t h0 = split2(w.x, w.y, &lx, &ly);
            uint32_t h1 = split2(w.z, w.w, &lz, &lw);
            const int w0 = seg*8 + q4*2;
            sW[row*132 + w0]          = h0;
            sW[row*132 + w0 + 1]      = h1;
            sW[row*132 + 64 + w0]     = cvt2_bf16(lx, ly);
            sW[row*132 + 64 + w0 + 1] = cvt2_bf16(lz, lw);
        }
    }
    if (tid < 32) sbo[tid] = bo[tid];
    __syncthreads();

    const int warp = tid >> 5, lane = tid & 31;
    const int l4 = lane & 3, ld4 = lane >> 2;
    const int m0 = blockIdx.x * 256 + warp * 32;

    float acc[2][4][4];
    #pragma unroll
    for (int mt = 0; mt < 2; ++mt)
    #pragma unroll
    for (int nt = 0; nt < 4; ++nt)
    #pragma unroll
    for (int u = 0; u < 4; ++u) acc[mt][nt][u] = 0.f;

    const uint32_t* A = (const uint32_t*)g_ohl;

    #pragma unroll
    for (int kc = 0; kc < 4; ++kc) {
        uint32_t Ah[2][2][4], Al[2][2][4];
        #pragma unroll
        for (int mt = 0; mt < 2; ++mt)
        #pragma unroll
        for (int kt = 0; kt < 2; ++kt) {
            const uint32_t* p0 = A + (size_t)(m0 + mt*16 + ld4) * 128 + kc*16 + kt*8 + l4;
            const uint32_t* p1 = p0 + 8*128;
            Ah[mt][kt][0] = p0[0];  Ah[mt][kt][1] = p1[0];
            Ah[mt][kt][2] = p0[4];  Ah[mt][kt][3] = p1[4];
            Al[mt][kt][0] = p0[64]; Al[mt][kt][1] = p1[64];
            Al[mt][kt][2] = p0[68]; Al[mt][kt][3] = p1[68];
        }
        #pragma unroll
        for (int nt = 0; nt < 4; ++nt) {
            const uint32_t* wp = sW + (nt*8 + ld4)*132 + kc*16 + l4;
            uint32_t bh[2][2], bl[2][2];
            bh[0][0]=wp[0];  bh[0][1]=wp[4];  bh[1][0]=wp[8];  bh[1][1]=wp[12];
            bl[0][0]=wp[64]; bl[0][1]=wp[68]; bl[1][0]=wp[72]; bl[1][1]=wp[76];
            #pragma unroll
            for (int mt = 0; mt < 2; ++mt) {
                #pragma unroll
                for (int kt = 0; kt < 2; ++kt) {
                    mma16816(acc[mt][nt], Ah[mt][kt], bh[kt][0], bh[kt][1]);
                    mma16816(acc[mt][nt], Ah[mt][kt], bl[kt][0], bl[kt][1]);
                    mma16816(acc[mt][nt], Al[mt][kt], bh[kt][0], bh[kt][1]);
                }
            }
        }
    }

    #pragma unroll
    for (int mt = 0; mt < 2; ++mt) {
        const int r0 = m0 + mt*16 + ld4;
        #pragma unroll
        for (int nt = 0; nt < 4; ++nt) {
            const int c0 = nt*8 + l4*2;
            *(float2*)(out + (size_t)r0*32 + c0) =
                make_float2(acc[mt][nt][0] + sbo[c0], acc[mt][nt][1] + sbo[c0+1]);
            *(float2*)(out + (size_t)(r0+8)*32 + c0) =
                make_float2(acc[mt][nt][2] + sbo[c0], acc[mt][nt][3] + sbo[c0+1]);
        }
    }
}

// ---------------------------------------------------------------------------
extern "C" void kernel_launch(void* const* d_in, const int* in_sizes, int n_in,
                              void* d_out, int out_size) {
    const float* z    = (const float*)d_in[0];
    const float* ln_g = (const float*)d_in[1];
    const float* ln_b = (const float*)d_in[2];
    const float* Wq   = (const float*)d_in[3];
    const float* Wk   = (const float*)d_in[4];
    const float* Wv   = (const float*)d_in[5];
    // d_in[6] = Wb: bias is constant along the softmax axis -> cancels exactly
    const float* Wg   = (const float*)d_in[7];
    const float* bg   = (const float*)d_in[8];
    const float* Wo   = (const float*)d_in[9];
    const float* bo   = (const float*)d_in[10];
    float* out = (float*)d_out;

    cudaFuncSetAttribute(attn_kernel, cudaFuncAttributeMaxDynamicSharedMemorySize, 70656);

    ln_kernel<<<256, 256>>>(z, ln_g, ln_b);
    projmm_kernel<<<4096, 256>>>(Wq, Wk, Wv, Wg, bg);
    attn_kernel<<<1024, 256, 70656>>>();
    outmm_kernel<<<256, 256>>>(Wo, bo, out);
}